// round 14
// baseline (speedup 1.0000x reference)
#include <cuda_runtime.h>
#include <cuda_bf16.h>
#include <cuda_fp16.h>
#include <math.h>
#include <stddef.h>
#include <stdint.h>

// Triangle multiplicative update (outgoing), N=512, cz=ch=128, fp32 in/out.
// All GEMMs on tensor cores via mma.sync bf16 hi/lo split (3 passes, fp32 acc).
// Round 14: k1 weight staging pipelined in 64-row halves (depth-1 cp.async
//           pipeline, zero extra smem); k2/k3 unchanged from round 13.

#define NSEQ 512
#define CDIM 128
#define NN   (NSEQ*NSEQ)          // 262144
#define PIT  136                  // bf16 smem pitch (elements)
#define PITB 272                  // bytes
#define XPIT 72                   // k3 X tile pitch (elements)
#define NT   512

__device__ __nv_bfloat16 g_a_hi[(size_t)CDIM * NN];
__device__ __nv_bfloat16 g_a_lo[(size_t)CDIM * NN];
__device__ __nv_bfloat16 g_b_hi[(size_t)CDIM * NN];
__device__ __nv_bfloat16 g_b_lo[(size_t)CDIM * NN];
__device__ __half g_g[(size_t)NN * CDIM];           // g[pix][c] fp16
__device__ __nv_bfloat16 g_xh[(size_t)CDIM * NN];   // x hi [c][i][j]
__device__ __nv_bfloat16 g_xl[(size_t)CDIM * NN];   // x lo
// pre-split weights: 0=lgate 1=left 2=rgate 3=right 4=gate 5=out(.scaled)
__device__ __align__(16) __nv_bfloat16 g_wh[6 * 16384];
__device__ __align__(16) __nv_bfloat16 g_wl[6 * 16384];
__device__ float g_u[128];   // sum_c s[c]*w_out[c][n]
__device__ float g_v[128];   // sum_c b_ln[c]*w_out[c][n]

__device__ __forceinline__ float sigmf(float x) {
    return 1.0f / (1.0f + __expf(-x));
}
__device__ __forceinline__ unsigned pk_bf16x2(float a, float b) {
    __nv_bfloat162 t = __floats2bfloat162_rn(a, b);
    return *reinterpret_cast<unsigned*>(&t);
}
__device__ __forceinline__ float bf16_res(float v) {   // v - bf16(v)
    return v - __bfloat162float(__float2bfloat16(v));
}
__device__ __forceinline__ uint32_t smem_u32(const void* p) {
    uint32_t a;
    asm("{ .reg .u64 t; cvta.to.shared.u64 t, %1; cvt.u32.u64 %0, t; }"
        : "=r"(a) : "l"(p));
    return a;
}
__device__ __forceinline__ void cp16(uint32_t dst, const void* src) {
    asm volatile("cp.async.cg.shared.global [%0], [%1], 16;"
                 :: "r"(dst), "l"(src) : "memory");
}
#define CP_COMMIT() asm volatile("cp.async.commit_group;" ::: "memory")
#define CP_WAIT0()  asm volatile("cp.async.wait_group 0;" ::: "memory")
#define CP_WAIT1()  asm volatile("cp.async.wait_group 1;" ::: "memory")
#define SWZ(o)   ((o) ^ (((o) >> 3) & 0x70))
#define SWZ64(o) ((o) ^ (((o) >> 3) & 0x30))

__device__ __forceinline__ void ldsm4(uint32_t addr, uint32_t* r) {
    asm volatile("ldmatrix.sync.aligned.m8n8.x4.shared.b16 {%0,%1,%2,%3}, [%4];"
                 : "=r"(r[0]), "=r"(r[1]), "=r"(r[2]), "=r"(r[3]) : "r"(addr));
}
__device__ __forceinline__ void ldsm4_t(uint32_t addr, uint32_t* r) {
    asm volatile("ldmatrix.sync.aligned.m8n8.x4.trans.shared.b16 {%0,%1,%2,%3}, [%4];"
                 : "=r"(r[0]), "=r"(r[1]), "=r"(r[2]), "=r"(r[3]) : "r"(addr));
}
__device__ __forceinline__ void mma_bf16(float* c, const uint32_t* a,
                                         const uint32_t* b) {
    asm volatile(
        "mma.sync.aligned.m16n8k16.row.col.f32.bf16.bf16.f32 "
        "{%0,%1,%2,%3}, {%4,%5,%6,%7}, {%8,%9}, {%0,%1,%2,%3};"
        : "+f"(c[0]), "+f"(c[1]), "+f"(c[2]), "+f"(c[3])
        : "r"(a[0]), "r"(a[1]), "r"(a[2]), "r"(a[3]), "r"(b[0]), "r"(b[1]));
}

__device__ __forceinline__ void split4(float4 v, uint2& hv, uint2& lv) {
    hv.x = pk_bf16x2(v.x, v.y);
    hv.y = pk_bf16x2(v.z, v.w);
    lv.x = pk_bf16x2(bf16_res(v.x), bf16_res(v.y));
    lv.y = pk_bf16x2(bf16_res(v.z), bf16_res(v.w));
}

// ---------------------------------------------------------------------------
// Kernel 0: pre-split 6 weight matrices (w_out pre-scaled by ln_out_scale),
// plus u/v fold vectors.
// ---------------------------------------------------------------------------
__global__ void __launch_bounds__(256)
k0_split(const float* __restrict__ w0, const float* __restrict__ w1,
         const float* __restrict__ w2, const float* __restrict__ w3,
         const float* __restrict__ w4, const float* __restrict__ w5,
         const float* __restrict__ so, const float* __restrict__ bo)
{
    if (blockIdx.x == 96) {
        int n = threadIdx.x;
        if (n < 128) {
            float u = 0.f, v = 0.f;
            for (int c = 0; c < 128; ++c) {
                float w = w5[c * 128 + n];
                u += so[c] * w;
                v += bo[c] * w;
            }
            g_u[n] = u; g_v[n] = v;
        }
        return;
    }
    const float* ws[6] = {w0, w1, w2, w3, w4, w5};
    int idx = blockIdx.x * 256 + threadIdx.x;
    int m = idx >> 12;
    int e = (idx & 4095) * 4;
    float4 v = *(const float4*)(ws[m] + e);
    if (m == 5) {
        float sc = so[e >> 7];
        v.x *= sc; v.y *= sc; v.z *= sc; v.w *= sc;
    }
    uint2 hv, lv;
    split4(v, hv, lv);
    *(uint2*)(g_wh + m * 16384 + e) = hv;
    *(uint2*)(g_wl + m * 16384 + e) = lv;
}

// ---------------------------------------------------------------------------
// Kernel 1: 256 threads, 64-pixel tiles, 2 CTAs/SM. Weight staging pipelined
// in 64-k-row halves: while GEMM runs on one half, the next half loads.
// 10 halves: (lgate,left,rgate,right,gate) x (k0:64, k64:128).
// ---------------------------------------------------------------------------
__global__ void __launch_bounds__(256, 2)
k1_all(const float* __restrict__ z, const float* __restrict__ mask,
       const float* __restrict__ ln_s, const float* __restrict__ ln_b,
       const float* __restrict__ b_lg, const float* __restrict__ b_l,
       const float* __restrict__ b_rg, const float* __restrict__ b_r,
       const float* __restrict__ b_g)
{
    extern __shared__ char smraw[];
    __nv_bfloat16* znh = (__nv_bfloat16*)smraw;          // [p<64][k] pitch 136
    __nv_bfloat16* znl = znh + 64 * PIT;
    __nv_bfloat16* B0h = znl + 64 * PIT;                 // khalf 0 buffer
    __nv_bfloat16* B0l = B0h + 64 * PIT;
    __nv_bfloat16* B1h = B0l + 64 * PIT;                 // khalf 1 buffer
    __nv_bfloat16* B1l = B1h + 64 * PIT;
    float* bs = (float*)(B1l + 64 * PIT);
    // bs: [0)lg [128)l [256)rg [384)r [512)g [640)mask(64)

    const int tid = threadIdx.x, lane = tid & 31, wid = tid >> 5;
    const int pix0 = blockIdx.x * 64;

    const uint32_t b0h = smem_u32(B0h), b0l = smem_u32(B0l);
    const uint32_t b1h = smem_u32(B1h), b1l = smem_u32(B1l);
    const uint32_t zh = smem_u32(znh), zl = smem_u32(znl);

    // stage one 64-row half of matrix mi into (dsth,dstl); one commit group.
#define STAGE_H(mi, kh, dsth, dstl)                                           \
    do {                                                                      \
        const __nv_bfloat16* SH = g_wh + (mi) * 16384 + (kh) * 8192;          \
        const __nv_bfloat16* SL = g_wl + (mi) * 16384 + (kh) * 8192;          \
        _Pragma("unroll")                                                     \
        for (int t = 0; t < 4; ++t) {                                         \
            int u = tid + t * 256;   /* 1024 chunks */                        \
            int r = u >> 4, c = u & 15;                                       \
            uint32_t doff = (uint32_t)(r * PITB + c * 16);                    \
            int goff = r * 128 + c * 8;                                       \
            cp16((dsth) + doff, SH + goff);                                   \
            cp16((dstl) + doff, SL + goff);                                   \
        }                                                                     \
        CP_COMMIT();                                                          \
    } while (0)

    STAGE_H(0, 0, b0h, b0l);   // group 0
    STAGE_H(0, 1, b1h, b1l);   // group 1

    bs[tid]       = (tid < 128) ? b_lg[tid] : b_l[tid - 128];
    bs[256 + tid] = (tid < 128) ? b_rg[tid] : b_r[tid - 128];
    if (tid < 128) bs[512 + tid] = b_g[tid];
    if (tid < 64)  bs[640 + tid] = mask[pix0 + tid];

    // LayerNorm: 8 warps, 8 rows each (overlaps with weight cp.async)
    {
        float4 s4 = ((const float4*)ln_s)[lane];
        float4 b4 = ((const float4*)ln_b)[lane];
        float4 v[8];
#pragma unroll
        for (int t = 0; t < 8; ++t)
            v[t] = ((const float4*)(z + (size_t)(pix0 + t * 8 + wid) * CDIM))[lane];
#pragma unroll
        for (int t = 0; t < 8; ++t) {
            int r = t * 8 + wid;
            float s  = v[t].x + v[t].y + v[t].z + v[t].w;
            float ss = v[t].x*v[t].x + v[t].y*v[t].y + v[t].z*v[t].z + v[t].w*v[t].w;
#pragma unroll
            for (int o = 16; o > 0; o >>= 1) {
                s  += __shfl_xor_sync(0xffffffffu, s,  o);
                ss += __shfl_xor_sync(0xffffffffu, ss, o);
            }
            float mu   = s * 0.0078125f;
            float rstd = rsqrtf(ss * 0.0078125f - mu * mu + 1e-5f);
            float4 o4;
            o4.x = (v[t].x - mu) * rstd * s4.x + b4.x;
            o4.y = (v[t].y - mu) * rstd * s4.y + b4.y;
            o4.z = (v[t].z - mu) * rstd * s4.z + b4.z;
            o4.w = (v[t].w - mu) * rstd * s4.w + b4.w;
            uint2 hv, lv;
            split4(o4, hv, lv);
            *(uint2*)(&znh[r * PIT + lane * 4]) = hv;
            *(uint2*)(&znl[r * PIT + lane * 4]) = lv;
        }
    }

    // gated warp grid: wm (ch) in [0,4), wn (p) in [0,2)
    const int wm = wid & 3, wn = wid >> 2;
    const int at_row = (lane & 7) + ((lane >> 4) << 3);      // trans A (W^T)
    const int at_col = ((lane >> 3) & 1) << 3;
    const int bp_row = wn * 32 + (lane & 7) + ((lane >> 4) << 3);  // B (zn)
    const uint32_t bko = ((lane >> 3) & 1) * 16;

    // one 64-k half of a gated GEMM (3 sweeps) into ACC[2][4][4]
#define GEMM_H(ACC, WHB, WLB, KH)                                             \
    do {                                                                      \
        _Pragma("unroll")                                                     \
        for (int k16 = 0; k16 < 4; ++k16) {                                   \
            const int kbz = ((KH) * 4 + k16) * 16;                            \
            const int kbw = k16 * 16;                                         \
            uint32_t bh[4][2], bl[4][2];                                      \
            _Pragma("unroll")                                                 \
            for (int ng = 0; ng < 2; ++ng) {                                  \
                uint32_t r4[4];                                               \
                uint32_t boff = (uint32_t)((bp_row + ng * 16) * PITB)         \
                                + kbz * 2 + bko;                              \
                ldsm4(zh + boff, r4);                                         \
                bh[ng*2][0] = r4[0]; bh[ng*2][1] = r4[1];                     \
                bh[ng*2+1][0] = r4[2]; bh[ng*2+1][1] = r4[3];                 \
                ldsm4(zl + boff, r4);                                         \
                bl[ng*2][0] = r4[0]; bl[ng*2][1] = r4[1];                     \
                bl[ng*2+1][0] = r4[2]; bl[ng*2+1][1] = r4[3];                 \
            }                                                                 \
            uint32_t aoff[2];                                                 \
            _Pragma("unroll")                                                 \
            for (int mt = 0; mt < 2; ++mt)                                    \
                aoff[mt] = (uint32_t)((kbw + at_row) * PITB) +                \
                           (wm * 32 + mt * 16 + at_col) * 2;                  \
            uint32_t a4[2][4];                                                \
            _Pragma("unroll")                                                 \
            for (int mt = 0; mt < 2; ++mt) ldsm4_t((WHB) + aoff[mt], a4[mt]); \
            _Pragma("unroll")                                                 \
            for (int mt = 0; mt < 2; ++mt)                                    \
                _Pragma("unroll")                                             \
                for (int nt = 0; nt < 4; ++nt)                                \
                    mma_bf16(ACC[mt][nt], a4[mt], bh[nt]);                    \
            _Pragma("unroll")                                                 \
            for (int mt = 0; mt < 2; ++mt)                                    \
                _Pragma("unroll")                                             \
                for (int nt = 0; nt < 4; ++nt)                                \
                    mma_bf16(ACC[mt][nt], a4[mt], bl[nt]);                    \
            _Pragma("unroll")                                                 \
            for (int mt = 0; mt < 2; ++mt) ldsm4_t((WLB) + aoff[mt], a4[mt]); \
            _Pragma("unroll")                                                 \
            for (int mt = 0; mt < 2; ++mt)                                    \
                _Pragma("unroll")                                             \
                for (int nt = 0; nt < 4; ++nt)                                \
                    mma_bf16(ACC[mt][nt], a4[mt], bh[nt]);                    \
        }                                                                     \
    } while (0)

    float P[2][4][4], Q[2][4][4];
#pragma unroll
    for (int a = 0; a < 2; ++a)
#pragma unroll
        for (int b = 0; b < 4; ++b)
#pragma unroll
            for (int q = 0; q < 4; ++q) { P[a][b][q] = 0.f; Q[a][b][q] = 0.f; }

    // epilogue for gated phase ph (0->a, 1->b); also resets P,Q
#define EPI(ph)                                                               \
    do {                                                                      \
        const float* bgp = bs + (ph) * 256;                                   \
        const float* bvp = bs + (ph) * 256 + 128;                             \
        const float* msm = bs + 640;                                          \
        __nv_bfloat16* oh = ((ph) == 0) ? g_a_hi : g_b_hi;                    \
        __nv_bfloat16* ol = ((ph) == 0) ? g_a_lo : g_b_lo;                    \
        _Pragma("unroll")                                                     \
        for (int mt = 0; mt < 2; ++mt) {                                      \
            int ch = wm * 32 + mt * 16 + (lane >> 2);                         \
            float bg0v = bgp[ch], bg1v = bgp[ch + 8];                         \
            float bv0v = bvp[ch], bv1v = bvp[ch + 8];                         \
            size_t r0 = (size_t)ch * NN + pix0;                               \
            size_t r1 = (size_t)(ch + 8) * NN + pix0;                         \
            _Pragma("unroll")                                                 \
            for (int nt = 0; nt < 4; ++nt) {                                  \
                int p = wn * 32 + nt * 8 + (lane & 3) * 2;                    \
                float m0 = msm[p], m1 = msm[p + 1];                           \
                float v00 = m0 * sigmf(P[mt][nt][0] + bg0v) * (Q[mt][nt][0] + bv0v); \
                float v01 = m1 * sigmf(P[mt][nt][1] + bg0v) * (Q[mt][nt][1] + bv0v); \
                float v10 = m0 * sigmf(P[mt][nt][2] + bg1v) * (Q[mt][nt][2] + bv1v); \
                float v11 = m1 * sigmf(P[mt][nt][3] + bg1v) * (Q[mt][nt][3] + bv1v); \
                *(uint32_t*)(oh + r0 + p) = pk_bf16x2(v00, v01);              \
                *(uint32_t*)(ol + r0 + p) = pk_bf16x2(bf16_res(v00), bf16_res(v01)); \
                *(uint32_t*)(oh + r1 + p) = pk_bf16x2(v10, v11);              \
                *(uint32_t*)(ol + r1 + p) = pk_bf16x2(bf16_res(v10), bf16_res(v11)); \
                P[mt][nt][0] = 0.f; P[mt][nt][1] = 0.f;                       \
                P[mt][nt][2] = 0.f; P[mt][nt][3] = 0.f;                       \
                Q[mt][nt][0] = 0.f; Q[mt][nt][1] = 0.f;                       \
                Q[mt][nt][2] = 0.f; Q[mt][nt][3] = 0.f;                       \
            }                                                                 \
        }                                                                     \
    } while (0)

    // ---- pipelined half schedule ----
    // group g uses buffer (g&1); before gemm on group g, issued = g+2.
    // P_A (lgate, groups 0,1)
    CP_WAIT1(); __syncthreads();
    GEMM_H(P, b0h, b0l, 0);
    __syncthreads();
    STAGE_H(1, 0, b0h, b0l);            // group 2 (left k0)
    CP_WAIT1(); __syncthreads();
    GEMM_H(P, b1h, b1l, 1);
    __syncthreads();
    STAGE_H(1, 1, b1h, b1l);            // group 3 (left k1)
    // Q_A (left, groups 2,3)
    CP_WAIT1(); __syncthreads();
    GEMM_H(Q, b0h, b0l, 0);
    __syncthreads();
    STAGE_H(2, 0, b0h, b0l);            // group 4 (rgate k0)
    CP_WAIT1(); __syncthreads();
    GEMM_H(Q, b1h, b1l, 1);
    __syncthreads();
    STAGE_H(2, 1, b1h, b1l);            // group 5 (rgate k1)
    EPI(0);                             // a epilogue (rgate loads in flight)
    // P_B (rgate, groups 4,5)
    CP_WAIT1(); __syncthreads();
    GEMM_H(P, b0h, b0l, 0);
    __syncthreads();
    STAGE_H(3, 0, b0h, b0l);            // group 6 (right k0)
    CP_WAIT1(); __syncthreads();
    GEMM_H(P, b1h, b1l, 1);
    __syncthreads();
    STAGE_H(3, 1, b1h, b1l);            // group 7 (right k1)
    // Q_B (right, groups 6,7)
    CP_WAIT1(); __syncthreads();
    GEMM_H(Q, b0h, b0l, 0);
    __syncthreads();
    STAGE_H(4, 0, b0h, b0l);            // group 8 (gate k0)
    CP_WAIT1(); __syncthreads();
    GEMM_H(Q, b1h, b1l, 1);
    __syncthreads();
    STAGE_H(4, 1, b1h, b1l);            // group 9 (gate k1)
    EPI(1);                             // b epilogue (gate loads in flight)

    // ---- phase C: g = sig(zn @ Wg + bg), C[p][ch], fp16 out ----
    {
        const int wm2 = wid & 1, wn2 = wid >> 1;   // 2 (p) x 4 (ch)
        const int a_row = wm2 * 32 + (lane & 15);
        const uint32_t ako = (lane >> 4) * 16;
        const int bt_row = (lane & 7) + (((lane >> 3) & 1) << 3);
        const int bt_col = (lane >> 4) << 3;

#define GEMMC_H(WHB, WLB, KH)                                                 \
    do {                                                                      \
        _Pragma("unroll")                                                     \
        for (int k16 = 0; k16 < 4; ++k16) {                                   \
            const int kbz = ((KH) * 4 + k16) * 16;                            \
            const int kbw = k16 * 16;                                         \
            uint32_t bh[4][2], bl[4][2];                                      \
            _Pragma("unroll")                                                 \
            for (int ng = 0; ng < 2; ++ng) {                                  \
                uint32_t r4[4];                                               \
                uint32_t boff = (uint32_t)((kbw + bt_row) * PITB) +           \
                                (wn2 * 32 + ng * 16 + bt_col) * 2;            \
                ldsm4_t((WHB) + boff, r4);                                    \
                bh[ng*2][0] = r4[0]; bh[ng*2][1] = r4[1];                     \
                bh[ng*2+1][0] = r4[2]; bh[ng*2+1][1] = r4[3];                 \
                ldsm4_t((WLB) + boff, r4);                                    \
                bl[ng*2][0] = r4[0]; bl[ng*2][1] = r4[1];                     \
                bl[ng*2+1][0] = r4[2]; bl[ng*2+1][1] = r4[3];                 \
            }                                                                 \
            uint32_t ah[2][4], al[2][4];                                      \
            _Pragma("unroll")                                                 \
            for (int mt = 0; mt < 2; ++mt) {                                  \
                uint32_t aoff = (uint32_t)((a_row + mt * 16) * PITB)          \
                                + kbz * 2 + ako;                              \
                ldsm4(zh + aoff, ah[mt]);                                     \
                ldsm4(zl + aoff, al[mt]);                                     \
            }                                                                 \
            _Pragma("unroll")                                                 \
            for (int mt = 0; mt < 2; ++mt)                                    \
                _Pragma("unroll")                                             \
                for (int nt = 0; nt < 4; ++nt)                                \
                    mma_bf16(P[mt][nt], ah[mt], bh[nt]);                      \
            _Pragma("unroll")                                                 \
            for (int mt = 0; mt < 2; ++mt)                                    \
                _Pragma("unroll")                                             \
                for (int nt = 0; nt < 4; ++nt)                                \
                    mma_bf16(P[mt][nt], ah[mt], bl[nt]);                      \
            _Pragma("unroll")                                                 \
            for (int mt = 0; mt < 2; ++mt)                                    \
                _Pragma("unroll")                                             \
                for (int nt = 0; nt < 4; ++nt)                                \
                    mma_bf16(P[mt][nt], al[mt], bh[nt]);                      \
        }                                                                     \
    } while (0)

        CP_WAIT1(); __syncthreads();
        GEMMC_H(b0h, b0l, 0);
        CP_WAIT0(); __syncthreads();
        GEMMC_H(b1h, b1l, 1);

        const float* bgp = bs + 512;
#pragma unroll
        for (int mt = 0; mt < 2; ++mt) {
            int p0 = pix0 + wm2 * 32 + mt * 16 + (lane >> 2);
#pragma unroll
            for (int nt = 0; nt < 4; ++nt) {
                int ch = wn2 * 32 + nt * 8 + (lane & 3) * 2;
                float b0 = bgp[ch], b1 = bgp[ch + 1];
                __half2 v0 = __floats2half2_rn(sigmf(P[mt][nt][0] + b0),
                                               sigmf(P[mt][nt][1] + b1));
                __half2 v1 = __floats2half2_rn(sigmf(P[mt][nt][2] + b0),
                                               sigmf(P[mt][nt][3] + b1));
                *(__half2*)(g_g + (size_t)p0 * CDIM + ch) = v0;
                *(__half2*)(g_g + (size_t)(p0 + 8) * CDIM + ch) = v1;
            }
        }
#undef GEMMC_H
    }
#undef EPI
#undef GEMM_H
#undef STAGE_H
}

// ---------------------------------------------------------------------------
// Kernel 2: per-channel X_c = A_c @ B_c^T. 256 threads, 2 CTAs/SM.
// (unchanged from round 13)
// ---------------------------------------------------------------------------
#define K2S 32768u

__global__ void __launch_bounds__(256, 2)
k2_mma()
{
    extern __shared__ char sm2[];
    const uint32_t smb = smem_u32(sm2);
    const int tid  = threadIdx.x;
    const int lane = tid & 31, wid = tid >> 5;
    const int wm = wid & 1, wn = wid >> 1;
    const int i0 = blockIdx.x * 128, j0 = blockIdx.y * 128;
    const size_t cbase = (size_t)blockIdx.z * NN;

    const __nv_bfloat16* Ah = g_a_hi + cbase + (size_t)i0 * NSEQ;
    const __nv_bfloat16* Al = g_a_lo + cbase + (size_t)i0 * NSEQ;
    const __nv_bfloat16* Bh = g_b_hi + cbase + (size_t)j0 * NSEQ;
    const __nv_bfloat16* Bl = g_b_lo + cbase + (size_t)j0 * NSEQ;

    float acc[4][4][4];
#pragma unroll
    for (int mt = 0; mt < 4; ++mt)
#pragma unroll
        for (int nt = 0; nt < 4; ++nt)
#pragma unroll
            for (int q = 0; q < 4; ++q) acc[mt][nt][q] = 0.f;

    const int arow = wm * 64 + (lane & 15);
    const int bnr  = wn * 32 + (lane & 7) + ((lane >> 4) << 3);
    const uint32_t a_koff = (uint32_t)((lane >> 4) << 4);
    const uint32_t b_koff = (uint32_t)(((lane >> 3) & 1) << 4);

#define K2_LOAD(kc, stg)                                                      \
    do {                                                                      \
        const int ke = (kc) * 32;                                             \
        _Pragma("unroll")                                                     \
        for (int t = 0; t < 2; ++t) {                                         \
            int v = tid + t * 256; int r = v >> 2, cu = v & 3;                \
            uint32_t so = SWZ64((uint32_t)(r * 64 + cu * 16));                \
            const size_t go = (size_t)r * NSEQ + ke + cu * 8;                 \
            cp16((stg) + so,           Ah + go);                              \
            cp16((stg) + 8192u + so,   Al + go);                              \
            cp16((stg) + 16384u + so,  Bh + go);                              \
            cp16((stg) + 24576u + so,  Bl + go);                              \
        }                                                                     \
        asm volatile("cp.async.commit_group;" ::: "memory");                  \
    } while (0)

    K2_LOAD(0, smb);
    K2_LOAD(1, smb + K2S);

#pragma unroll 1
    for (int kc = 0; kc < 16; ++kc) {
        if (kc < 15) asm volatile("cp.async.wait_group 1;" ::: "memory");
        else         asm volatile("cp.async.wait_group 0;" ::: "memory");
        __syncthreads();
        const uint32_t stg = smb + (uint32_t)(kc % 3) * K2S;

#pragma unroll
        for (int k16 = 0; k16 < 2; ++k16) {
            const uint32_t kbA = (uint32_t)(k16 * 32) + a_koff;
            const uint32_t kbB = (uint32_t)(k16 * 32) + b_koff;
            uint32_t bh[4][2], bl[4][2];
#pragma unroll
            for (int ng = 0; ng < 2; ++ng) {
                uint32_t r4[4];
                uint32_t off = SWZ64((uint32_t)((bnr + ng * 16) * 64) + kbB);
                ldsm4(stg + 16384u + off, r4);
                bh[ng * 2 + 0][0] = r4[0]; bh[ng * 2 + 0][1] = r4[1];
                bh[ng * 2 + 1][0] = r4[2]; bh[ng * 2 + 1][1] = r4[3];
                ldsm4(stg + 24576u + off, r4);
                bl[ng * 2 + 0][0] = r4[0]; bl[ng * 2 + 0][1] = r4[1];
                bl[ng * 2 + 1][0] = r4[2]; bl[ng * 2 + 1][1] = r4[3];
            }
            uint32_t aoff[4];
#pragma unroll
            for (int mt = 0; mt < 4; ++mt)
                aoff[mt] = SWZ64((uint32_t)((arow + mt * 16) * 64) + kbA);
            uint32_t a4[4][4];
#pragma unroll
            for (int mt = 0; mt < 4; ++mt) ldsm4(stg + aoff[mt], a4[mt]);
#pragma unroll
            for (int mt = 0; mt < 4; ++mt)
#pragma unroll
                for (int nt = 0; nt < 4; ++nt)
                    mma_bf16(acc[mt][nt], a4[mt], bh[nt]);
#pragma unroll
            for (int mt = 0; mt < 4; ++mt)
#pragma unroll
                for (int nt = 0; nt < 4; ++nt)
                    mma_bf16(acc[mt][nt], a4[mt], bl[nt]);
#pragma unroll
            for (int mt = 0; mt < 4; ++mt) ldsm4(stg + 8192u + aoff[mt], a4[mt]);
#pragma unroll
            for (int mt = 0; mt < 4; ++mt)
#pragma unroll
                for (int nt = 0; nt < 4; ++nt)
                    mma_bf16(acc[mt][nt], a4[mt], bh[nt]);
        }
        if (kc + 2 < 16) K2_LOAD(kc + 2, smb + (uint32_t)((kc + 2) % 3) * K2S);
    }

    __nv_bfloat16* Xh = g_xh + cbase + (size_t)(i0 + wm * 64) * NSEQ + j0 + wn * 32;
    __nv_bfloat16* Xl = g_xl + cbase + (size_t)(i0 + wm * 64) * NSEQ + j0 + wn * 32;
    const int rr = lane >> 2, cc = (lane & 3) * 2;
#pragma unroll
    for (int mt = 0; mt < 4; ++mt)
#pragma unroll
        for (int nt = 0; nt < 4; ++nt) {
            size_t o0 = (size_t)(mt * 16 + rr) * NSEQ + nt * 8 + cc;
            size_t o1 = o0 + 8 * NSEQ;
            float v0 = acc[mt][nt][0], v1 = acc[mt][nt][1];
            float v2 = acc[mt][nt][2], v3 = acc[mt][nt][3];
            *(uint32_t*)(Xh + o0) = pk_bf16x2(v0, v1);
            *(uint32_t*)(Xl + o0) = pk_bf16x2(bf16_res(v0), bf16_res(v1));
            *(uint32_t*)(Xh + o1) = pk_bf16x2(v2, v3);
            *(uint32_t*)(Xl + o1) = pk_bf16x2(bf16_res(v2), bf16_res(v3));
        }
#undef K2_LOAD
}

// ---------------------------------------------------------------------------
// Kernel 3: folded-LN out projection, 256 threads, 64-pixel tiles, 2 CTAs/SM.
// (unchanged from round 13)
// ---------------------------------------------------------------------------
__global__ void __launch_bounds__(256, 2)
k3_mma(const float* __restrict__ b_out, float* __restrict__ out)
{
    extern __shared__ char smraw[];
    __nv_bfloat16* Xh = (__nv_bfloat16*)smraw;          // [c][p<64] pitch 72
    __nv_bfloat16* Xl = Xh + 128 * XPIT;
    __nv_bfloat16* Wh = Xl + 128 * XPIT;                // [k][n] pitch 136
    __nv_bfloat16* Wl = Wh + 128 * PIT;
    float* uS   = (float*)(Wl + 128 * PIT);
    float* wS   = uS + 128;
    float* redS = wS + 128;      // 256
    float* redQ = redS + 256;    // 256
    float* rsS  = redQ + 256;    // 64
    float* tS   = rsS + 64;      // 64

    const int tid = threadIdx.x, lane = tid & 31, wid = tid >> 5;
    const int pix0 = blockIdx.x * 64;

    {
        const uint32_t xhA = smem_u32(Xh), xlA = smem_u32(Xl);
        const uint32_t whA = smem_u32(Wh), wlA = smem_u32(Wl);
        const __nv_bfloat16* GH = g_wh + 5 * 16384;
        const __nv_bfloat16* GL = g_wl + 5 * 16384;
#pragma unroll
        for (int t = 0; t < 4; ++t) {
            int u = tid + t * 256;
            int c = u >> 3, q = u & 7;
            uint32_t doff = (uint32_t)(c * (XPIT * 2) + q * 16);
            size_t goff = (size_t)c * NN + pix0 + q * 8;
            cp16(xhA + doff, g_xh + goff);
            cp16(xlA + doff, g_xl + goff);
        }
#pragma unroll
        for (int t = 0; t < 8; ++t) {
            int u = tid + t * 256;
            int r = u >> 4, c = u & 15;
            uint32_t doff = (uint32_t)(r * PITB + c * 16);
            int goff = r * 128 + c * 8;
            cp16(whA + doff, GH + goff);
            cp16(wlA + doff, GL + goff);
        }
        CP_COMMIT();
    }
    if (tid < 128) { uS[tid] = g_u[tid]; wS[tid] = g_v[tid] + b_out[tid]; }
    CP_WAIT0();
    __syncthreads();

    const int p = tid & 63, quarter = tid >> 6;
    {
        float s = 0.f, ss = 0.f;
#pragma unroll 8
        for (int c = quarter * 32; c < quarter * 32 + 32; ++c) {
            float v = __bfloat162float(Xh[c * XPIT + p]) +
                      __bfloat162float(Xl[c * XPIT + p]);
            s += v; ss += v * v;
        }
        redS[tid] = s; redQ[tid] = ss;
    }
    __syncthreads();
    if (tid < 64) {
        float S  = redS[tid] + redS[tid + 64] + redS[tid + 128] + redS[tid + 192];
        float Qv = redQ[tid] + redQ[tid + 64] + redQ[tid + 128] + redQ[tid + 192];
        float mu = S * 0.0078125f;
        float rs = rsqrtf(Qv * 0.0078125f - mu * mu + 1e-5f);
        rsS[tid] = rs;
        tS[tid]  = mu * rs;
    }
    __syncthreads();

    const int wm = wid & 1, wn = wid >> 1;
    const uint32_t xh = smem_u32(Xh), xl = smem_u32(Xl);
    const uint32_t wh = smem_u32(Wh), wl = smem_u32(Wl);

    float acc[2][4][4];
#pragma unroll
    for (int a = 0; a < 2; ++a)
#pragma unroll
        for (int b = 0; b < 4; ++b)
#pragma unroll
            for (int q = 0; q < 4; ++q) acc[a][b][q] = 0.f;

    const int at_row = (lane & 7) + ((lane >> 4) << 3);
    const int at_col = ((lane >> 3) & 1) << 3;
    const int bt_row = (lane & 7) + (((lane >> 3) & 1) << 3);
    const int bt_col = (lane >> 4) << 3;

#pragma unroll
    for (int k16 = 0; k16 < 8; ++k16) {
        const int kb = k16 * 16;
        uint32_t bh[4][2], bl[4][2];
#pragma unroll
        for (int ng = 0; ng < 2; ++ng) {
            uint32_t r4[4];
            uint32_t boff = (uint32_t)((kb + bt_row) * PITB) +
                            (wn * 32 + ng * 16 + bt_col) * 2;
            ldsm4_t(wh + boff, r4);
            bh[ng*2][0] = r4[0]; bh[ng*2][1] = r4[1];
            bh[ng*2+1][0] = r4[2]; bh[ng*2+1][1] = r4[3];
            ldsm4_t(wl + boff, r4);
            bl[ng*2][0] = r4[0]; bl[ng*2][1] = r4[1];
            bl[ng*2+1][0] = r4[2]; bl[ng*2+1][1] = r4[3];
        }
        uint32_t ah[2][4], al[2][4];
#pragma unroll
        for (int mt = 0; mt < 2; ++mt) {
            uint32_t aoff = (uint32_t)((kb + at_row) * (XPIT * 2)) +
                            (wm * 32 + mt * 16 + at_col) * 2;
            ldsm4_t(xh + aoff, ah[mt]);
            ldsm4_t(xl + aoff, al[mt]);
        }
#pragma unroll
        for (int mt = 0; mt < 2; ++mt)
#pragma unroll
            for (int nt = 0; nt < 4; ++nt)
                mma_bf16(acc[mt][nt], ah[mt], bh[nt]);
#pragma unroll
        for (int mt = 0; mt < 2; ++mt)
#pragma unroll
            for (int nt = 0; nt < 4; ++nt)
                mma_bf16(acc[mt][nt], ah[mt], bl[nt]);
#pragma unroll
        for (int mt = 0; mt < 2; ++mt)
#pragma unroll
            for (int nt = 0; nt < 4; ++nt)
                mma_bf16(acc[mt][nt], al[mt], bh[nt]);
    }

#pragma unroll
    for (int mt = 0; mt < 2; ++mt) {
        int pl = wm * 32 + mt * 16 + (lane >> 2);
        int p0 = pix0 + pl;
        float rs0 = rsS[pl],     t0 = tS[pl];
        float rs1 = rsS[pl + 8], t1 = tS[pl + 8];
#pragma unroll
        for (int nt = 0; nt < 4; ++nt) {
            int ch = wn * 32 + nt * 8 + (lane & 3) * 2;
            float u0 = uS[ch], u1 = uS[ch + 1];
            float w0 = wS[ch], w1 = wS[ch + 1];
            float2 g0 = __half22float2(
                *(const __half2*)(g_g + (size_t)p0 * CDIM + ch));
            float2 g1 = __half22float2(
                *(const __half2*)(g_g + (size_t)(p0 + 8) * CDIM + ch));
            float2 v0 = make_float2((rs0 * acc[mt][nt][0] - t0 * u0 + w0) * g0.x,
                                    (rs0 * acc[mt][nt][1] - t0 * u1 + w1) * g0.y);
            float2 v1 = make_float2((rs1 * acc[mt][nt][2] - t1 * u0 + w0) * g1.x,
                                    (rs1 * acc[mt][nt][3] - t1 * u1 + w1) * g1.y);
            *(float2*)(out + (size_t)p0 * CDIM + ch) = v0;
            *(float2*)(out + (size_t)(p0 + 8) * CDIM + ch) = v1;
        }
    }
}

// ---------------------------------------------------------------------------
extern "C" void kernel_launch(void* const* d_in, const int* in_sizes, int n_in,
                              void* d_out, int out_size)
{
    const float* z        = (const float*)d_in[0];
    const float* mask     = (const float*)d_in[1];
    const float* ln_in_s  = (const float*)d_in[2];
    const float* ln_in_b  = (const float*)d_in[3];
    const float* w_left   = (const float*)d_in[4];
    const float* b_left   = (const float*)d_in[5];
    const float* w_right  = (const float*)d_in[6];
    const float* b_right  = (const float*)d_in[7];
    const float* w_lgate  = (const float*)d_in[8];
    const float* b_lgate  = (const float*)d_in[9];
    const float* w_rgate  = (const float*)d_in[10];
    const float* b_rgate  = (const float*)d_in[11];
    const float* ln_out_s = (const float*)d_in[12];
    const float* ln_out_b = (const float*)d_in[13];
    const float* w_out    = (const float*)d_in[14];
    const float* b_out    = (const float*)d_in[15];
    const float* w_gate   = (const float*)d_in[16];
    const float* b_gate   = (const float*)d_in[17];
    float* out = (float*)d_out;

    const int smem1 = 6 * 64 * PIT * 2 + 704 * 4;                          // ~107 KB
    const int smem2 = 3 * (int)K2S;                                        // 98304
    const int smem3 = (2 * 128 * XPIT + 2 * 128 * PIT) * 2 +
                      (2 * 128 + 2 * 256 + 2 * 64) * 4;                    // ~110 KB

    cudaFuncSetAttribute(k1_all, cudaFuncAttributeMaxDynamicSharedMemorySize, smem1);
    cudaFuncSetAttribute(k2_mma, cudaFuncAttributeMaxDynamicSharedMemorySize, smem2);
    cudaFuncSetAttribute(k3_mma, cudaFuncAttributeMaxDynamicSharedMemorySize, smem3);

    // 0) pre-split weights (w_out scaled by ln_out_scale) + u/v fold vectors
    k0_split<<<97, 256>>>(w_lgate, w_left, w_rgate, w_right, w_gate, w_out,
                          ln_out_s, ln_out_b);

    // 1) a, b, g projections from a single LN pass (2 CTAs/SM, piped weights)
    k1_all<<<NN / 64, 256, smem1>>>(
        z, mask, ln_in_s, ln_in_b,
        b_lgate, b_left, b_rgate, b_right, b_gate);

    // 2) triangular einsum per channel (2 CTAs/SM)
    k2_mma<<<dim3(4, 4, CDIM), 256, smem2>>>();

    // 3) folded-LN out projection + gating (2 CTAs/SM)
    k3_mma<<<NN / 64, 256, smem3>>>(b_out, out);
}

// round 15
// speedup vs baseline: 1.0079x; 1.0079x over previous
#include <cuda_runtime.h>
#include <cuda_bf16.h>
#include <cuda_fp16.h>
#include <math.h>
#include <stddef.h>
#include <stdint.h>

// Triangle multiplicative update (outgoing), N=512, cz=ch=128, fp32 in/out.
// All GEMMs on tensor cores via mma.sync bf16 hi/lo split (3 passes, fp32 acc).
// Round 15: k1 reverted to round-13 (serialized stages, 2 CTAs/SM);
//           k3 processes 2 tiles per CTA (W staged once, X1 load overlapped
//           with tile-0 epilogue; split commit groups so stats overlap W load).

#define NSEQ 512
#define CDIM 128
#define NN   (NSEQ*NSEQ)          // 262144
#define PIT  136                  // bf16 smem pitch (elements)
#define PITB 272                  // bytes
#define XPIT 72                   // k3 X tile pitch (elements)
#define NT   512

__device__ __nv_bfloat16 g_a_hi[(size_t)CDIM * NN];
__device__ __nv_bfloat16 g_a_lo[(size_t)CDIM * NN];
__device__ __nv_bfloat16 g_b_hi[(size_t)CDIM * NN];
__device__ __nv_bfloat16 g_b_lo[(size_t)CDIM * NN];
__device__ __half g_g[(size_t)NN * CDIM];           // g[pix][c] fp16
__device__ __nv_bfloat16 g_xh[(size_t)CDIM * NN];   // x hi [c][i][j]
__device__ __nv_bfloat16 g_xl[(size_t)CDIM * NN];   // x lo
// pre-split weights: 0=lgate 1=left 2=rgate 3=right 4=gate 5=out(.scaled)
__device__ __align__(16) __nv_bfloat16 g_wh[6 * 16384];
__device__ __align__(16) __nv_bfloat16 g_wl[6 * 16384];
__device__ float g_u[128];   // sum_c s[c]*w_out[c][n]
__device__ float g_v[128];   // sum_c b_ln[c]*w_out[c][n]

__device__ __forceinline__ float sigmf(float x) {
    return 1.0f / (1.0f + __expf(-x));
}
__device__ __forceinline__ unsigned pk_bf16x2(float a, float b) {
    __nv_bfloat162 t = __floats2bfloat162_rn(a, b);
    return *reinterpret_cast<unsigned*>(&t);
}
__device__ __forceinline__ float bf16_res(float v) {   // v - bf16(v)
    return v - __bfloat162float(__float2bfloat16(v));
}
__device__ __forceinline__ uint32_t smem_u32(const void* p) {
    uint32_t a;
    asm("{ .reg .u64 t; cvta.to.shared.u64 t, %1; cvt.u32.u64 %0, t; }"
        : "=r"(a) : "l"(p));
    return a;
}
__device__ __forceinline__ void cp16(uint32_t dst, const void* src) {
    asm volatile("cp.async.cg.shared.global [%0], [%1], 16;"
                 :: "r"(dst), "l"(src) : "memory");
}
#define CP_COMMIT() asm volatile("cp.async.commit_group;" ::: "memory")
#define CP_WAIT0()  asm volatile("cp.async.wait_group 0;" ::: "memory")
#define CP_WAIT1()  asm volatile("cp.async.wait_group 1;" ::: "memory")
#define SWZ(o)   ((o) ^ (((o) >> 3) & 0x70))
#define SWZ64(o) ((o) ^ (((o) >> 3) & 0x30))

__device__ __forceinline__ void ldsm4(uint32_t addr, uint32_t* r) {
    asm volatile("ldmatrix.sync.aligned.m8n8.x4.shared.b16 {%0,%1,%2,%3}, [%4];"
                 : "=r"(r[0]), "=r"(r[1]), "=r"(r[2]), "=r"(r[3]) : "r"(addr));
}
__device__ __forceinline__ void ldsm4_t(uint32_t addr, uint32_t* r) {
    asm volatile("ldmatrix.sync.aligned.m8n8.x4.trans.shared.b16 {%0,%1,%2,%3}, [%4];"
                 : "=r"(r[0]), "=r"(r[1]), "=r"(r[2]), "=r"(r[3]) : "r"(addr));
}
__device__ __forceinline__ void mma_bf16(float* c, const uint32_t* a,
                                         const uint32_t* b) {
    asm volatile(
        "mma.sync.aligned.m16n8k16.row.col.f32.bf16.bf16.f32 "
        "{%0,%1,%2,%3}, {%4,%5,%6,%7}, {%8,%9}, {%0,%1,%2,%3};"
        : "+f"(c[0]), "+f"(c[1]), "+f"(c[2]), "+f"(c[3])
        : "r"(a[0]), "r"(a[1]), "r"(a[2]), "r"(a[3]), "r"(b[0]), "r"(b[1]));
}

__device__ __forceinline__ void split4(float4 v, uint2& hv, uint2& lv) {
    hv.x = pk_bf16x2(v.x, v.y);
    hv.y = pk_bf16x2(v.z, v.w);
    lv.x = pk_bf16x2(bf16_res(v.x), bf16_res(v.y));
    lv.y = pk_bf16x2(bf16_res(v.z), bf16_res(v.w));
}

// ---------------------------------------------------------------------------
// Kernel 0: pre-split 6 weight matrices (w_out pre-scaled by ln_out_scale),
// plus u/v fold vectors.
// ---------------------------------------------------------------------------
__global__ void __launch_bounds__(256)
k0_split(const float* __restrict__ w0, const float* __restrict__ w1,
         const float* __restrict__ w2, const float* __restrict__ w3,
         const float* __restrict__ w4, const float* __restrict__ w5,
         const float* __restrict__ so, const float* __restrict__ bo)
{
    if (blockIdx.x == 96) {
        int n = threadIdx.x;
        if (n < 128) {
            float u = 0.f, v = 0.f;
            for (int c = 0; c < 128; ++c) {
                float w = w5[c * 128 + n];
                u += so[c] * w;
                v += bo[c] * w;
            }
            g_u[n] = u; g_v[n] = v;
        }
        return;
    }
    const float* ws[6] = {w0, w1, w2, w3, w4, w5};
    int idx = blockIdx.x * 256 + threadIdx.x;
    int m = idx >> 12;
    int e = (idx & 4095) * 4;
    float4 v = *(const float4*)(ws[m] + e);
    if (m == 5) {
        float sc = so[e >> 7];
        v.x *= sc; v.y *= sc; v.z *= sc; v.w *= sc;
    }
    uint2 hv, lv;
    split4(v, hv, lv);
    *(uint2*)(g_wh + m * 16384 + e) = hv;
    *(uint2*)(g_wl + m * 16384 + e) = lv;
}

// ---------------------------------------------------------------------------
// Kernel 1: 256 threads, 64-pixel tiles, 2 CTAs/SM. One weight pair resident.
// (round-13 version)
// ---------------------------------------------------------------------------
__global__ void __launch_bounds__(256, 2)
k1_all(const float* __restrict__ z, const float* __restrict__ mask,
       const float* __restrict__ ln_s, const float* __restrict__ ln_b,
       const float* __restrict__ b_lg, const float* __restrict__ b_l,
       const float* __restrict__ b_rg, const float* __restrict__ b_r,
       const float* __restrict__ b_g)
{
    extern __shared__ char smraw[];
    __nv_bfloat16* znh = (__nv_bfloat16*)smraw;          // [p<64][k] pitch 136
    __nv_bfloat16* znl = znh + 64 * PIT;
    __nv_bfloat16* Wh  = znl + 64 * PIT;                 // [k][n] pitch 136
    __nv_bfloat16* Wl  = Wh + 128 * PIT;
    float* bs = (float*)(Wl + 128 * PIT);
    // bs: [0)lg [128)l [256)rg [384)r [512)g [640)mask(64)

    const int tid = threadIdx.x, lane = tid & 31, wid = tid >> 5;
    const int pix0 = blockIdx.x * 64;

    const uint32_t whA = smem_u32(Wh), wlA = smem_u32(Wl);
    const uint32_t zh = smem_u32(znh), zl = smem_u32(znl);

#define STAGE_W(mi)                                                           \
    do {                                                                      \
        const __nv_bfloat16* SH = g_wh + (mi) * 16384;                        \
        const __nv_bfloat16* SL = g_wl + (mi) * 16384;                        \
        _Pragma("unroll")                                                     \
        for (int t = 0; t < 8; ++t) {                                         \
            int u = tid + t * 256;                                            \
            int r = u >> 4, c = u & 15;                                       \
            uint32_t doff = (uint32_t)(r * PITB + c * 16);                    \
            int goff = r * 128 + c * 8;                                       \
            cp16(whA + doff, SH + goff);                                      \
            cp16(wlA + doff, SL + goff);                                      \
        }                                                                     \
        CP_COMMIT();                                                          \
    } while (0)

    STAGE_W(0);   // lgate

    bs[tid]       = (tid < 128) ? b_lg[tid] : b_l[tid - 128];
    bs[256 + tid] = (tid < 128) ? b_rg[tid] : b_r[tid - 128];
    if (tid < 128) bs[512 + tid] = b_g[tid];
    if (tid < 64)  bs[640 + tid] = mask[pix0 + tid];

    // LayerNorm: 8 warps, 8 rows each (overlaps with weight cp.async)
    {
        float4 s4 = ((const float4*)ln_s)[lane];
        float4 b4 = ((const float4*)ln_b)[lane];
        float4 v[8];
#pragma unroll
        for (int t = 0; t < 8; ++t)
            v[t] = ((const float4*)(z + (size_t)(pix0 + t * 8 + wid) * CDIM))[lane];
#pragma unroll
        for (int t = 0; t < 8; ++t) {
            int r = t * 8 + wid;
            float s  = v[t].x + v[t].y + v[t].z + v[t].w;
            float ss = v[t].x*v[t].x + v[t].y*v[t].y + v[t].z*v[t].z + v[t].w*v[t].w;
#pragma unroll
            for (int o = 16; o > 0; o >>= 1) {
                s  += __shfl_xor_sync(0xffffffffu, s,  o);
                ss += __shfl_xor_sync(0xffffffffu, ss, o);
            }
            float mu   = s * 0.0078125f;
            float rstd = rsqrtf(ss * 0.0078125f - mu * mu + 1e-5f);
            float4 o4;
            o4.x = (v[t].x - mu) * rstd * s4.x + b4.x;
            o4.y = (v[t].y - mu) * rstd * s4.y + b4.y;
            o4.z = (v[t].z - mu) * rstd * s4.z + b4.z;
            o4.w = (v[t].w - mu) * rstd * s4.w + b4.w;
            uint2 hv, lv;
            split4(o4, hv, lv);
            *(uint2*)(&znh[r * PIT + lane * 4]) = hv;
            *(uint2*)(&znl[r * PIT + lane * 4]) = lv;
        }
    }
    CP_WAIT0();
    __syncthreads();

    const int wm = wid & 3, wn = wid >> 2;
    const int at_row = (lane & 7) + ((lane >> 4) << 3);
    const int at_col = ((lane >> 3) & 1) << 3;
    const int bp_row = wn * 32 + (lane & 7) + ((lane >> 4) << 3);
    const uint32_t bko = ((lane >> 3) & 1) * 16;

#define GEMM_W(ACC)                                                           \
    do {                                                                      \
        _Pragma("unroll")                                                     \
        for (int k16 = 0; k16 < 8; ++k16) {                                   \
            const int kb = k16 * 16;                                          \
            uint32_t bh[4][2], bl[4][2];                                      \
            _Pragma("unroll")                                                 \
            for (int ng = 0; ng < 2; ++ng) {                                  \
                uint32_t r4[4];                                               \
                uint32_t boff = (uint32_t)((bp_row + ng * 16) * PITB)         \
                                + kb * 2 + bko;                               \
                ldsm4(zh + boff, r4);                                         \
                bh[ng*2][0] = r4[0]; bh[ng*2][1] = r4[1];                     \
                bh[ng*2+1][0] = r4[2]; bh[ng*2+1][1] = r4[3];                 \
                ldsm4(zl + boff, r4);                                         \
                bl[ng*2][0] = r4[0]; bl[ng*2][1] = r4[1];                     \
                bl[ng*2+1][0] = r4[2]; bl[ng*2+1][1] = r4[3];                 \
            }                                                                 \
            uint32_t aoff[2];                                                 \
            _Pragma("unroll")                                                 \
            for (int mt = 0; mt < 2; ++mt)                                    \
                aoff[mt] = (uint32_t)((kb + at_row) * PITB) +                 \
                           (wm * 32 + mt * 16 + at_col) * 2;                  \
            uint32_t a4[2][4];                                                \
            _Pragma("unroll")                                                 \
            for (int mt = 0; mt < 2; ++mt) ldsm4_t(whA + aoff[mt], a4[mt]);   \
            _Pragma("unroll")                                                 \
            for (int mt = 0; mt < 2; ++mt)                                    \
                _Pragma("unroll")                                             \
                for (int nt = 0; nt < 4; ++nt)                                \
                    mma_bf16(ACC[mt][nt], a4[mt], bh[nt]);                    \
            _Pragma("unroll")                                                 \
            for (int mt = 0; mt < 2; ++mt)                                    \
                _Pragma("unroll")                                             \
                for (int nt = 0; nt < 4; ++nt)                                \
                    mma_bf16(ACC[mt][nt], a4[mt], bl[nt]);                    \
            _Pragma("unroll")                                                 \
            for (int mt = 0; mt < 2; ++mt) ldsm4_t(wlA + aoff[mt], a4[mt]);   \
            _Pragma("unroll")                                                 \
            for (int mt = 0; mt < 2; ++mt)                                    \
                _Pragma("unroll")                                             \
                for (int nt = 0; nt < 4; ++nt)                                \
                    mma_bf16(ACC[mt][nt], a4[mt], bh[nt]);                    \
        }                                                                     \
    } while (0)

    float P[2][4][4], Q[2][4][4];

#pragma unroll 1
    for (int ph = 0; ph < 2; ++ph) {
#pragma unroll
        for (int a = 0; a < 2; ++a)
#pragma unroll
            for (int b = 0; b < 4; ++b)
#pragma unroll
                for (int q = 0; q < 4; ++q) { P[a][b][q] = 0.f; Q[a][b][q] = 0.f; }

        GEMM_W(P);
        __syncthreads();
        STAGE_W(ph == 0 ? 1 : 3);
        CP_WAIT0();
        __syncthreads();
        GEMM_W(Q);
        __syncthreads();
        STAGE_W(ph == 0 ? 2 : 4);

        const float* bgp = bs + ph * 256;
        const float* bvp = bs + ph * 256 + 128;
        const float* msm = bs + 640;
        __nv_bfloat16* oh = (ph == 0) ? g_a_hi : g_b_hi;
        __nv_bfloat16* ol = (ph == 0) ? g_a_lo : g_b_lo;
#pragma unroll
        for (int mt = 0; mt < 2; ++mt) {
            int ch = wm * 32 + mt * 16 + (lane >> 2);
            float bg0v = bgp[ch], bg1v = bgp[ch + 8];
            float bv0v = bvp[ch], bv1v = bvp[ch + 8];
            size_t r0 = (size_t)ch * NN + pix0;
            size_t r1 = (size_t)(ch + 8) * NN + pix0;
#pragma unroll
            for (int nt = 0; nt < 4; ++nt) {
                int p = wn * 32 + nt * 8 + (lane & 3) * 2;
                float m0 = msm[p], m1 = msm[p + 1];
                float v00 = m0 * sigmf(P[mt][nt][0] + bg0v) * (Q[mt][nt][0] + bv0v);
                float v01 = m1 * sigmf(P[mt][nt][1] + bg0v) * (Q[mt][nt][1] + bv0v);
                float v10 = m0 * sigmf(P[mt][nt][2] + bg1v) * (Q[mt][nt][2] + bv1v);
                float v11 = m1 * sigmf(P[mt][nt][3] + bg1v) * (Q[mt][nt][3] + bv1v);
                *(uint32_t*)(oh + r0 + p) = pk_bf16x2(v00, v01);
                *(uint32_t*)(ol + r0 + p) = pk_bf16x2(bf16_res(v00), bf16_res(v01));
                *(uint32_t*)(oh + r1 + p) = pk_bf16x2(v10, v11);
                *(uint32_t*)(ol + r1 + p) = pk_bf16x2(bf16_res(v10), bf16_res(v11));
            }
        }
        CP_WAIT0();
        __syncthreads();
    }

    // ---- phase C: g = sig(zn @ Wg + bg), C[p][ch], fp16 out ----
    {
        const int wm2 = wid & 1, wn2 = wid >> 1;
        const int a_row = wm2 * 32 + (lane & 15);
        const uint32_t ako = (lane >> 4) * 16;
        const int bt_row = (lane & 7) + (((lane >> 3) & 1) << 3);
        const int bt_col = (lane >> 4) << 3;

#pragma unroll
        for (int a = 0; a < 2; ++a)
#pragma unroll
            for (int b = 0; b < 4; ++b)
#pragma unroll
                for (int q = 0; q < 4; ++q) P[a][b][q] = 0.f;

#pragma unroll
        for (int k16 = 0; k16 < 8; ++k16) {
            const int kb = k16 * 16;
            uint32_t bh[4][2], bl[4][2];
#pragma unroll
            for (int ng = 0; ng < 2; ++ng) {
                uint32_t r4[4];
                uint32_t boff = (uint32_t)((kb + bt_row) * PITB) +
                                (wn2 * 32 + ng * 16 + bt_col) * 2;
                ldsm4_t(whA + boff, r4);
                bh[ng*2][0] = r4[0]; bh[ng*2][1] = r4[1];
                bh[ng*2+1][0] = r4[2]; bh[ng*2+1][1] = r4[3];
                ldsm4_t(wlA + boff, r4);
                bl[ng*2][0] = r4[0]; bl[ng*2][1] = r4[1];
                bl[ng*2+1][0] = r4[2]; bl[ng*2+1][1] = r4[3];
            }
            uint32_t ah[2][4], al[2][4];
#pragma unroll
            for (int mt = 0; mt < 2; ++mt) {
                uint32_t aoff = (uint32_t)((a_row + mt * 16) * PITB) + kb * 2 + ako;
                ldsm4(zh + aoff, ah[mt]);
                ldsm4(zl + aoff, al[mt]);
            }
#pragma unroll
            for (int mt = 0; mt < 2; ++mt)
#pragma unroll
                for (int nt = 0; nt < 4; ++nt)
                    mma_bf16(P[mt][nt], ah[mt], bh[nt]);
#pragma unroll
            for (int mt = 0; mt < 2; ++mt)
#pragma unroll
                for (int nt = 0; nt < 4; ++nt)
                    mma_bf16(P[mt][nt], ah[mt], bl[nt]);
#pragma unroll
            for (int mt = 0; mt < 2; ++mt)
#pragma unroll
                for (int nt = 0; nt < 4; ++nt)
                    mma_bf16(P[mt][nt], al[mt], bh[nt]);
        }

        const float* bgp = bs + 512;
#pragma unroll
        for (int mt = 0; mt < 2; ++mt) {
            int p0 = pix0 + wm2 * 32 + mt * 16 + (lane >> 2);
#pragma unroll
            for (int nt = 0; nt < 4; ++nt) {
                int ch = wn2 * 32 + nt * 8 + (lane & 3) * 2;
                float b0 = bgp[ch], b1 = bgp[ch + 1];
                __half2 v0 = __floats2half2_rn(sigmf(P[mt][nt][0] + b0),
                                               sigmf(P[mt][nt][1] + b1));
                __half2 v1 = __floats2half2_rn(sigmf(P[mt][nt][2] + b0),
                                               sigmf(P[mt][nt][3] + b1));
                *(__half2*)(g_g + (size_t)p0 * CDIM + ch) = v0;
                *(__half2*)(g_g + (size_t)(p0 + 8) * CDIM + ch) = v1;
            }
        }
    }
#undef GEMM_W
#undef STAGE_W
}

// ---------------------------------------------------------------------------
// Kernel 2: per-channel X_c = A_c @ B_c^T. 256 threads, 2 CTAs/SM.
// (unchanged from round 13)
// ---------------------------------------------------------------------------
#define K2S 32768u

__global__ void __launch_bounds__(256, 2)
k2_mma()
{
    extern __shared__ char sm2[];
    const uint32_t smb = smem_u32(sm2);
    const int tid  = threadIdx.x;
    const int lane = tid & 31, wid = tid >> 5;
    const int wm = wid & 1, wn = wid >> 1;
    const int i0 = blockIdx.x * 128, j0 = blockIdx.y * 128;
    const size_t cbase = (size_t)blockIdx.z * NN;

    const __nv_bfloat16* Ah = g_a_hi + cbase + (size_t)i0 * NSEQ;
    const __nv_bfloat16* Al = g_a_lo + cbase + (size_t)i0 * NSEQ;
    const __nv_bfloat16* Bh = g_b_hi + cbase + (size_t)j0 * NSEQ;
    const __nv_bfloat16* Bl = g_b_lo + cbase + (size_t)j0 * NSEQ;

    float acc[4][4][4];
#pragma unroll
    for (int mt = 0; mt < 4; ++mt)
#pragma unroll
        for (int nt = 0; nt < 4; ++nt)
#pragma unroll
            for (int q = 0; q < 4; ++q) acc[mt][nt][q] = 0.f;

    const int arow = wm * 64 + (lane & 15);
    const int bnr  = wn * 32 + (lane & 7) + ((lane >> 4) << 3);
    const uint32_t a_koff = (uint32_t)((lane >> 4) << 4);
    const uint32_t b_koff = (uint32_t)(((lane >> 3) & 1) << 4);

#define K2_LOAD(kc, stg)                                                      \
    do {                                                                      \
        const int ke = (kc) * 32;                                             \
        _Pragma("unroll")                                                     \
        for (int t = 0; t < 2; ++t) {                                         \
            int v = tid + t * 256; int r = v >> 2, cu = v & 3;                \
            uint32_t so = SWZ64((uint32_t)(r * 64 + cu * 16));                \
            const size_t go = (size_t)r * NSEQ + ke + cu * 8;                 \
            cp16((stg) + so,           Ah + go);                              \
            cp16((stg) + 8192u + so,   Al + go);                              \
            cp16((stg) + 16384u + so,  Bh + go);                              \
            cp16((stg) + 24576u + so,  Bl + go);                              \
        }                                                                     \
        asm volatile("cp.async.commit_group;" ::: "memory");                  \
    } while (0)

    K2_LOAD(0, smb);
    K2_LOAD(1, smb + K2S);

#pragma unroll 1
    for (int kc = 0; kc < 16; ++kc) {
        if (kc < 15) asm volatile("cp.async.wait_group 1;" ::: "memory");
        else         asm volatile("cp.async.wait_group 0;" ::: "memory");
        __syncthreads();
        const uint32_t stg = smb + (uint32_t)(kc % 3) * K2S;

#pragma unroll
        for (int k16 = 0; k16 < 2; ++k16) {
            const uint32_t kbA = (uint32_t)(k16 * 32) + a_koff;
            const uint32_t kbB = (uint32_t)(k16 * 32) + b_koff;
            uint32_t bh[4][2], bl[4][2];
#pragma unroll
            for (int ng = 0; ng < 2; ++ng) {
                uint32_t r4[4];
                uint32_t off = SWZ64((uint32_t)((bnr + ng * 16) * 64) + kbB);
                ldsm4(stg + 16384u + off, r4);
                bh[ng * 2 + 0][0] = r4[0]; bh[ng * 2 + 0][1] = r4[1];
                bh[ng * 2 + 1][0] = r4[2]; bh[ng * 2 + 1][1] = r4[3];
                ldsm4(stg + 24576u + off, r4);
                bl[ng * 2 + 0][0] = r4[0]; bl[ng * 2 + 0][1] = r4[1];
                bl[ng * 2 + 1][0] = r4[2]; bl[ng * 2 + 1][1] = r4[3];
            }
            uint32_t aoff[4];
#pragma unroll
            for (int mt = 0; mt < 4; ++mt)
                aoff[mt] = SWZ64((uint32_t)((arow + mt * 16) * 64) + kbA);
            uint32_t a4[4][4];
#pragma unroll
            for (int mt = 0; mt < 4; ++mt) ldsm4(stg + aoff[mt], a4[mt]);
#pragma unroll
            for (int mt = 0; mt < 4; ++mt)
#pragma unroll
                for (int nt = 0; nt < 4; ++nt)
                    mma_bf16(acc[mt][nt], a4[mt], bh[nt]);
#pragma unroll
            for (int mt = 0; mt < 4; ++mt)
#pragma unroll
                for (int nt = 0; nt < 4; ++nt)
                    mma_bf16(acc[mt][nt], a4[mt], bl[nt]);
#pragma unroll
            for (int mt = 0; mt < 4; ++mt) ldsm4(stg + 8192u + aoff[mt], a4[mt]);
#pragma unroll
            for (int mt = 0; mt < 4; ++mt)
#pragma unroll
                for (int nt = 0; nt < 4; ++nt)
                    mma_bf16(acc[mt][nt], a4[mt], bh[nt]);
        }
        if (kc + 2 < 16) K2_LOAD(kc + 2, smb + (uint32_t)((kc + 2) % 3) * K2S);
    }

    __nv_bfloat16* Xh = g_xh + cbase + (size_t)(i0 + wm * 64) * NSEQ + j0 + wn * 32;
    __nv_bfloat16* Xl = g_xl + cbase + (size_t)(i0 + wm * 64) * NSEQ + j0 + wn * 32;
    const int rr = lane >> 2, cc = (lane & 3) * 2;
#pragma unroll
    for (int mt = 0; mt < 4; ++mt)
#pragma unroll
        for (int nt = 0; nt < 4; ++nt) {
            size_t o0 = (size_t)(mt * 16 + rr) * NSEQ + nt * 8 + cc;
            size_t o1 = o0 + 8 * NSEQ;
            float v0 = acc[mt][nt][0], v1 = acc[mt][nt][1];
            float v2 = acc[mt][nt][2], v3 = acc[mt][nt][3];
            *(uint32_t*)(Xh + o0) = pk_bf16x2(v0, v1);
            *(uint32_t*)(Xl + o0) = pk_bf16x2(bf16_res(v0), bf16_res(v1));
            *(uint32_t*)(Xh + o1) = pk_bf16x2(v2, v3);
            *(uint32_t*)(Xl + o1) = pk_bf16x2(bf16_res(v2), bf16_res(v3));
        }
#undef K2_LOAD
}

// ---------------------------------------------------------------------------
// Kernel 3: folded-LN out projection, 256 threads, TWO 64-pixel tiles per CTA
// (w_out staged once; X for tile 1 staged overlapping tile-0 epilogue).
// ---------------------------------------------------------------------------
__global__ void __launch_bounds__(256, 2)
k3_mma(const float* __restrict__ b_out, float* __restrict__ out)
{
    extern __shared__ char smraw[];
    __nv_bfloat16* Xh = (__nv_bfloat16*)smraw;          // [c][p<64] pitch 72
    __nv_bfloat16* Xl = Xh + 128 * XPIT;
    __nv_bfloat16* Wh = Xl + 128 * XPIT;                // [k][n] pitch 136
    __nv_bfloat16* Wl = Wh + 128 * PIT;
    float* uS   = (float*)(Wl + 128 * PIT);
    float* wS   = uS + 128;
    float* redS = wS + 128;      // 256
    float* redQ = redS + 256;    // 256
    float* rsS  = redQ + 256;    // 64
    float* tS   = rsS + 64;      // 64

    const int tid = threadIdx.x, lane = tid & 31, wid = tid >> 5;
    const int pix00 = blockIdx.x * 128;

    const uint32_t xhA = smem_u32(Xh), xlA = smem_u32(Xl);
    const uint32_t whA = smem_u32(Wh), wlA = smem_u32(Wl);

#define STAGE_X(px)                                                           \
    do {                                                                      \
        _Pragma("unroll")                                                     \
        for (int t = 0; t < 4; ++t) {                                         \
            int u = tid + t * 256;                                            \
            int c = u >> 3, q = u & 7;                                        \
            uint32_t doff = (uint32_t)(c * (XPIT * 2) + q * 16);              \
            size_t goff = (size_t)c * NN + (px) + q * 8;                      \
            cp16(xhA + doff, g_xh + goff);                                    \
            cp16(xlA + doff, g_xl + goff);                                    \
        }                                                                     \
        CP_COMMIT();                                                          \
    } while (0)

    // group 0: X tile 0 ; group 1: W
    STAGE_X(pix00);
    {
        const __nv_bfloat16* GH = g_wh + 5 * 16384;
        const __nv_bfloat16* GL = g_wl + 5 * 16384;
#pragma unroll
        for (int t = 0; t < 8; ++t) {
            int u = tid + t * 256;
            int r = u >> 4, c = u & 15;
            uint32_t doff = (uint32_t)(r * PITB + c * 16);
            int goff = r * 128 + c * 8;
            cp16(whA + doff, GH + goff);
            cp16(wlA + doff, GL + goff);
        }
        CP_COMMIT();
    }
    if (tid < 128) { uS[tid] = g_u[tid]; wS[tid] = g_v[tid] + b_out[tid]; }

    const int p = tid & 63, quarter = tid >> 6;
    const int wm = wid & 1, wn = wid >> 1;
    const int at_row = (lane & 7) + ((lane >> 4) << 3);
    const int at_col = ((lane >> 3) & 1) << 3;
    const int bt_row = (lane & 7) + (((lane >> 3) & 1) << 3);
    const int bt_col = (lane >> 4) << 3;

    CP_WAIT1();          // X tile 0 ready (W may still be in flight)
    __syncthreads();

#pragma unroll 1
    for (int tile = 0; tile < 2; ++tile) {
        const int pix0 = pix00 + tile * 64;

        // stats over c (four threads per pixel, 32 channels each)
        {
            float s = 0.f, ss = 0.f;
#pragma unroll 8
            for (int c = quarter * 32; c < quarter * 32 + 32; ++c) {
                float v = __bfloat162float(Xh[c * XPIT + p]) +
                          __bfloat162float(Xl[c * XPIT + p]);
                s += v; ss += v * v;
            }
            redS[tid] = s; redQ[tid] = ss;
        }
        __syncthreads();
        if (tid < 64) {
            float S  = redS[tid] + redS[tid + 64] + redS[tid + 128] + redS[tid + 192];
            float Qv = redQ[tid] + redQ[tid + 64] + redQ[tid + 128] + redQ[tid + 192];
            float mu = S * 0.0078125f;
            float rs = rsqrtf(Qv * 0.0078125f - mu * mu + 1e-5f);
            rsS[tid] = rs;
            tS[tid]  = mu * rs;
        }
        if (tile == 0) CP_WAIT0();   // W ready (overlapped with stats)
        __syncthreads();

        float acc[2][4][4];
#pragma unroll
        for (int a = 0; a < 2; ++a)
#pragma unroll
            for (int b = 0; b < 4; ++b)
#pragma unroll
                for (int q = 0; q < 4; ++q) acc[a][b][q] = 0.f;

#pragma unroll
        for (int k16 = 0; k16 < 8; ++k16) {
            const int kb = k16 * 16;
            uint32_t bh[4][2], bl[4][2];
#pragma unroll
            for (int ng = 0; ng < 2; ++ng) {
                uint32_t r4[4];
                uint32_t boff = (uint32_t)((kb + bt_row) * PITB) +
                                (wn * 32 + ng * 16 + bt_col) * 2;
                ldsm4_t(whA + boff, r4);
                bh[ng*2][0] = r4[0]; bh[ng*2][1] = r4[1];
                bh[ng*2+1][0] = r4[2]; bh[ng*2+1][1] = r4[3];
                ldsm4_t(wlA + boff, r4);
                bl[ng*2][0] = r4[0]; bl[ng*2][1] = r4[1];
                bl[ng*2+1][0] = r4[2]; bl[ng*2+1][1] = r4[3];
            }
            uint32_t ah[2][4], al[2][4];
#pragma unroll
            for (int mt = 0; mt < 2; ++mt) {
                uint32_t aoff = (uint32_t)((kb + at_row) * (XPIT * 2)) +
                                (wm * 32 + mt * 16 + at_col) * 2;
                ldsm4_t(xhA + aoff, ah[mt]);
                ldsm4_t(xlA + aoff, al[mt]);
            }
#pragma unroll
            for (int mt = 0; mt < 2; ++mt)
#pragma unroll
                for (int nt = 0; nt < 4; ++nt)
                    mma_bf16(acc[mt][nt], ah[mt], bh[nt]);
#pragma unroll
            for (int mt = 0; mt < 2; ++mt)
#pragma unroll
                for (int nt = 0; nt < 4; ++nt)
                    mma_bf16(acc[mt][nt], ah[mt], bl[nt]);
#pragma unroll
            for (int mt = 0; mt < 2; ++mt)
#pragma unroll
                for (int nt = 0; nt < 4; ++nt)
                    mma_bf16(acc[mt][nt], al[mt], bh[nt]);
        }

        if (tile == 0) {
            __syncthreads();            // all warps done reading X tile 0
            STAGE_X(pix00 + 64);        // overlaps with epilogue below
        }

        // epilogue: y = rs*acc - t*u + w ; out = y * g (g fp16 from L2)
#pragma unroll
        for (int mt = 0; mt < 2; ++mt) {
            int pl = wm * 32 + mt * 16 + (lane >> 2);
            int p0 = pix0 + pl;
            float rs0 = rsS[pl],     t0 = tS[pl];
            float rs1 = rsS[pl + 8], t1 = tS[pl + 8];
#pragma unroll
            for (int nt = 0; nt < 4; ++nt) {
                int ch = wn * 32 + nt * 8 + (lane & 3) * 2;
                float u0 = uS[ch], u1 = uS[ch + 1];
                float w0 = wS[ch], w1 = wS[ch + 1];
                float2 g0 = __half22float2(
                    *(const __half2*)(g_g + (size_t)p0 * CDIM + ch));
                float2 g1 = __half22float2(
                    *(const __half2*)(g_g + (size_t)(p0 + 8) * CDIM + ch));
                float2 v0 = make_float2((rs0 * acc[mt][nt][0] - t0 * u0 + w0) * g0.x,
                                        (rs0 * acc[mt][nt][1] - t0 * u1 + w1) * g0.y);
                float2 v1 = make_float2((rs1 * acc[mt][nt][2] - t1 * u0 + w0) * g1.x,
                                        (rs1 * acc[mt][nt][3] - t1 * u1 + w1) * g1.y);
                *(float2*)(out + (size_t)p0 * CDIM + ch) = v0;
                *(float2*)(out + (size_t)(p0 + 8) * CDIM + ch) = v1;
            }
        }

        if (tile == 0) {
            CP_WAIT0();                 // X tile 1 ready
            __syncthreads();
        }
    }
#undef STAGE_X
}

// ---------------------------------------------------------------------------
extern "C" void kernel_launch(void* const* d_in, const int* in_sizes, int n_in,
                              void* d_out, int out_size)
{
    const float* z        = (const float*)d_in[0];
    const float* mask     = (const float*)d_in[1];
    const float* ln_in_s  = (const float*)d_in[2];
    const float* ln_in_b  = (const float*)d_in[3];
    const float* w_left   = (const float*)d_in[4];
    const float* b_left   = (const float*)d_in[5];
    const float* w_right  = (const float*)d_in[6];
    const float* b_right  = (const float*)d_in[7];
    const float* w_lgate  = (const float*)d_in[8];
    const float* b_lgate  = (const float*)d_in[9];
    const float* w_rgate  = (const float*)d_in[10];
    const float* b_rgate  = (const float*)d_in[11];
    const float* ln_out_s = (const float*)d_in[12];
    const float* ln_out_b = (const float*)d_in[13];
    const float* w_out    = (const float*)d_in[14];
    const float* b_out    = (const float*)d_in[15];
    const float* w_gate   = (const float*)d_in[16];
    const float* b_gate   = (const float*)d_in[17];
    float* out = (float*)d_out;

    const int smem1 = (64 * PIT + 64 * PIT + 2 * 128 * PIT) * 2 + 704 * 4; // ~107 KB
    const int smem2 = 3 * (int)K2S;                                        // 98304
    const int smem3 = (2 * 128 * XPIT + 2 * 128 * PIT) * 2 +
                      (2 * 128 + 2 * 256 + 2 * 64) * 4;                    // ~110 KB

    cudaFuncSetAttribute(k1_all, cudaFuncAttributeMaxDynamicSharedMemorySize, smem1);
    cudaFuncSetAttribute(k2_mma, cudaFuncAttributeMaxDynamicSharedMemorySize, smem2);
    cudaFuncSetAttribute(k3_mma, cudaFuncAttributeMaxDynamicSharedMemorySize, smem3);

    // 0) pre-split weights (w_out scaled by ln_out_scale) + u/v fold vectors
    k0_split<<<97, 256>>>(w_lgate, w_left, w_rgate, w_right, w_gate, w_out,
                          ln_out_s, ln_out_b);

    // 1) a, b, g projections from a single LN pass (2 CTAs/SM)
    k1_all<<<NN / 64, 256, smem1>>>(
        z, mask, ln_in_s, ln_in_b,
        b_lgate, b_left, b_rgate, b_right, b_gate);

    // 2) triangular einsum per channel (2 CTAs/SM)
    k2_mma<<<dim3(4, 4, CDIM), 256, smem2>>>();

    // 3) folded-LN out projection + gating (2 CTAs/SM, 2 tiles per CTA)
    k3_mma<<<NN / 128, 256, smem3>>>(b_out, out);
}

// round 16
// speedup vs baseline: 1.1520x; 1.1430x over previous
#include <cuda_runtime.h>
#include <cuda_bf16.h>
#include <cuda_fp16.h>
#include <math.h>
#include <stddef.h>
#include <stdint.h>

// Triangle multiplicative update (outgoing), N=512, cz=ch=128, fp32 in/out.
// Round 16: k1 uses fp16 weights (single) + fp16 hi/lo zn -> 2-sweep GEMMs,
//           double-buffered weight staging. k3 reverted to round-13. k2 frozen.

#define NSEQ 512
#define CDIM 128
#define NN   (NSEQ*NSEQ)          // 262144
#define PIT  136                  // 16-bit smem pitch (elements)
#define PITB 272                  // bytes
#define XPIT 72                   // k3 X tile pitch (elements)
#define NT   512

__device__ __nv_bfloat16 g_a_hi[(size_t)CDIM * NN];
__device__ __nv_bfloat16 g_a_lo[(size_t)CDIM * NN];
__device__ __nv_bfloat16 g_b_hi[(size_t)CDIM * NN];
__device__ __nv_bfloat16 g_b_lo[(size_t)CDIM * NN];
__device__ __half g_g[(size_t)NN * CDIM];           // g[pix][c] fp16
__device__ __nv_bfloat16 g_xh[(size_t)CDIM * NN];   // x hi [c][i][j]
__device__ __nv_bfloat16 g_xl[(size_t)CDIM * NN];   // x lo
// fp16 projection weights: 0=lgate 1=left 2=rgate 3=right 4=gate
__device__ __align__(16) __half g_wf[5 * 16384];
// bf16 hi/lo scaled w_out (for k3)
__device__ __align__(16) __nv_bfloat16 g_wh[16384];
__device__ __align__(16) __nv_bfloat16 g_wl[16384];
__device__ float g_u[128];   // sum_c s[c]*w_out[c][n]
__device__ float g_v[128];   // sum_c b_ln[c]*w_out[c][n]

__device__ __forceinline__ float sigmf(float x) {
    return 1.0f / (1.0f + __expf(-x));
}
__device__ __forceinline__ unsigned pk_bf16x2(float a, float b) {
    __nv_bfloat162 t = __floats2bfloat162_rn(a, b);
    return *reinterpret_cast<unsigned*>(&t);
}
__device__ __forceinline__ float bf16_res(float v) {   // v - bf16(v)
    return v - __bfloat162float(__float2bfloat16(v));
}
__device__ __forceinline__ float f16_res(float v) {    // v - fp16(v)
    return v - __half2float(__float2half_rn(v));
}
__device__ __forceinline__ uint32_t smem_u32(const void* p) {
    uint32_t a;
    asm("{ .reg .u64 t; cvta.to.shared.u64 t, %1; cvt.u32.u64 %0, t; }"
        : "=r"(a) : "l"(p));
    return a;
}
__device__ __forceinline__ void cp16(uint32_t dst, const void* src) {
    asm volatile("cp.async.cg.shared.global [%0], [%1], 16;"
                 :: "r"(dst), "l"(src) : "memory");
}
#define CP_COMMIT() asm volatile("cp.async.commit_group;" ::: "memory")
#define CP_WAIT0()  asm volatile("cp.async.wait_group 0;" ::: "memory")
#define CP_WAIT1()  asm volatile("cp.async.wait_group 1;" ::: "memory")
#define SWZ(o)   ((o) ^ (((o) >> 3) & 0x70))
#define SWZ64(o) ((o) ^ (((o) >> 3) & 0x30))

__device__ __forceinline__ void ldsm4(uint32_t addr, uint32_t* r) {
    asm volatile("ldmatrix.sync.aligned.m8n8.x4.shared.b16 {%0,%1,%2,%3}, [%4];"
                 : "=r"(r[0]), "=r"(r[1]), "=r"(r[2]), "=r"(r[3]) : "r"(addr));
}
__device__ __forceinline__ void ldsm4_t(uint32_t addr, uint32_t* r) {
    asm volatile("ldmatrix.sync.aligned.m8n8.x4.trans.shared.b16 {%0,%1,%2,%3}, [%4];"
                 : "=r"(r[0]), "=r"(r[1]), "=r"(r[2]), "=r"(r[3]) : "r"(addr));
}
__device__ __forceinline__ void mma_bf16(float* c, const uint32_t* a,
                                         const uint32_t* b) {
    asm volatile(
        "mma.sync.aligned.m16n8k16.row.col.f32.bf16.bf16.f32 "
        "{%0,%1,%2,%3}, {%4,%5,%6,%7}, {%8,%9}, {%0,%1,%2,%3};"
        : "+f"(c[0]), "+f"(c[1]), "+f"(c[2]), "+f"(c[3])
        : "r"(a[0]), "r"(a[1]), "r"(a[2]), "r"(a[3]), "r"(b[0]), "r"(b[1]));
}
__device__ __forceinline__ void mma_f16(float* c, const uint32_t* a,
                                        const uint32_t* b) {
    asm volatile(
        "mma.sync.aligned.m16n8k16.row.col.f32.f16.f16.f32 "
        "{%0,%1,%2,%3}, {%4,%5,%6,%7}, {%8,%9}, {%0,%1,%2,%3};"
        : "+f"(c[0]), "+f"(c[1]), "+f"(c[2]), "+f"(c[3])
        : "r"(a[0]), "r"(a[1]), "r"(a[2]), "r"(a[3]), "r"(b[0]), "r"(b[1]));
}

__device__ __forceinline__ void split4(float4 v, uint2& hv, uint2& lv) {
    hv.x = pk_bf16x2(v.x, v.y);
    hv.y = pk_bf16x2(v.z, v.w);
    lv.x = pk_bf16x2(bf16_res(v.x), bf16_res(v.y));
    lv.y = pk_bf16x2(bf16_res(v.z), bf16_res(v.w));
}
__device__ __forceinline__ unsigned pk_h2(float a, float b) {
    __half2 t = __floats2half2_rn(a, b);
    return *reinterpret_cast<unsigned*>(&t);
}
__device__ __forceinline__ void split4h(float4 v, uint2& hv, uint2& lv) {
    hv.x = pk_h2(v.x, v.y);
    hv.y = pk_h2(v.z, v.w);
    lv.x = pk_h2(f16_res(v.x), f16_res(v.y));
    lv.y = pk_h2(f16_res(v.z), f16_res(v.w));
}

// ---------------------------------------------------------------------------
// Kernel 0: 5 projection weights -> fp16; w_out (scaled) -> bf16 hi/lo; u/v.
// ---------------------------------------------------------------------------
__global__ void __launch_bounds__(256)
k0_split(const float* __restrict__ w0, const float* __restrict__ w1,
         const float* __restrict__ w2, const float* __restrict__ w3,
         const float* __restrict__ w4, const float* __restrict__ w5,
         const float* __restrict__ so, const float* __restrict__ bo)
{
    if (blockIdx.x == 96) {
        int n = threadIdx.x;
        if (n < 128) {
            float u = 0.f, v = 0.f;
            for (int c = 0; c < 128; ++c) {
                float w = w5[c * 128 + n];
                u += so[c] * w;
                v += bo[c] * w;
            }
            g_u[n] = u; g_v[n] = v;
        }
        return;
    }
    const float* ws[6] = {w0, w1, w2, w3, w4, w5};
    int idx = blockIdx.x * 256 + threadIdx.x;
    int m = idx >> 12;
    int e = (idx & 4095) * 4;
    float4 v = *(const float4*)(ws[m] + e);
    if (m < 5) {
        __half2 h0 = __floats2half2_rn(v.x, v.y);
        __half2 h1 = __floats2half2_rn(v.z, v.w);
        *(__half2*)(g_wf + m * 16384 + e)     = h0;
        *(__half2*)(g_wf + m * 16384 + e + 2) = h1;
    } else {
        float sc = so[e >> 7];
        v.x *= sc; v.y *= sc; v.z *= sc; v.w *= sc;
        uint2 hv, lv;
        split4(v, hv, lv);
        *(uint2*)(g_wh + e) = hv;
        *(uint2*)(g_wl + e) = lv;
    }
}

// ---------------------------------------------------------------------------
// Kernel 1: 256 threads, 64-pixel tiles, 2 CTAs/SM.
// fp16 weights (single), fp16 hi/lo zn, 2-sweep GEMMs, double-buffered W.
// ---------------------------------------------------------------------------
__global__ void __launch_bounds__(256, 2)
k1_all(const float* __restrict__ z, const float* __restrict__ mask,
       const float* __restrict__ ln_s, const float* __restrict__ ln_b,
       const float* __restrict__ b_lg, const float* __restrict__ b_l,
       const float* __restrict__ b_rg, const float* __restrict__ b_r,
       const float* __restrict__ b_g)
{
    extern __shared__ char smraw[];
    __half* znh = (__half*)smraw;                 // [p<64][k] pitch 136
    __half* znl = znh + 64 * PIT;
    __half* W0  = znl + 64 * PIT;                 // [k][n] pitch 136
    __half* W1  = W0 + 128 * PIT;
    float* bs = (float*)(W1 + 128 * PIT);
    // bs: [0)lg [128)l [256)rg [384)r [512)g [640)mask(64)

    const int tid = threadIdx.x, lane = tid & 31, wid = tid >> 5;
    const int pix0 = blockIdx.x * 64;

    const uint32_t w0A = smem_u32(W0), w1A = smem_u32(W1);
    const uint32_t zh = smem_u32(znh), zl = smem_u32(znl);

#define STAGE_W(mi, dstA)                                                     \
    do {                                                                      \
        const __half* S = g_wf + (mi) * 16384;                                \
        _Pragma("unroll")                                                     \
        for (int t = 0; t < 8; ++t) {                                         \
            int u = tid + t * 256;                                            \
            int r = u >> 4, c = u & 15;                                       \
            uint32_t doff = (uint32_t)(r * PITB + c * 16);                    \
            int goff = r * 128 + c * 8;                                       \
            cp16((dstA) + doff, S + goff);                                    \
        }                                                                     \
        CP_COMMIT();                                                          \
    } while (0)

    STAGE_W(0, w0A);   // group 0: lgate
    STAGE_W(1, w1A);   // group 1: left

    bs[tid]       = (tid < 128) ? b_lg[tid] : b_l[tid - 128];
    bs[256 + tid] = (tid < 128) ? b_rg[tid] : b_r[tid - 128];
    if (tid < 128) bs[512 + tid] = b_g[tid];
    if (tid < 64)  bs[640 + tid] = mask[pix0 + tid];

    // LayerNorm: 8 warps, 8 rows each (overlaps with weight cp.async)
    {
        float4 s4 = ((const float4*)ln_s)[lane];
        float4 b4 = ((const float4*)ln_b)[lane];
        float4 v[8];
#pragma unroll
        for (int t = 0; t < 8; ++t)
            v[t] = ((const float4*)(z + (size_t)(pix0 + t * 8 + wid) * CDIM))[lane];
#pragma unroll
        for (int t = 0; t < 8; ++t) {
            int r = t * 8 + wid;
            float s  = v[t].x + v[t].y + v[t].z + v[t].w;
            float ss = v[t].x*v[t].x + v[t].y*v[t].y + v[t].z*v[t].z + v[t].w*v[t].w;
#pragma unroll
            for (int o = 16; o > 0; o >>= 1) {
                s  += __shfl_xor_sync(0xffffffffu, s,  o);
                ss += __shfl_xor_sync(0xffffffffu, ss, o);
            }
            float mu   = s * 0.0078125f;
            float rstd = rsqrtf(ss * 0.0078125f - mu * mu + 1e-5f);
            float4 o4;
            o4.x = (v[t].x - mu) * rstd * s4.x + b4.x;
            o4.y = (v[t].y - mu) * rstd * s4.y + b4.y;
            o4.z = (v[t].z - mu) * rstd * s4.z + b4.z;
            o4.w = (v[t].w - mu) * rstd * s4.w + b4.w;
            uint2 hv, lv;
            split4h(o4, hv, lv);
            *(uint2*)(&znh[r * PIT + lane * 4]) = hv;
            *(uint2*)(&znl[r * PIT + lane * 4]) = lv;
        }
    }

    // gated warp grid: wm (ch) in [0,4), wn (p) in [0,2)
    const int wm = wid & 3, wn = wid >> 2;
    const int at_row = (lane & 7) + ((lane >> 4) << 3);      // trans A (W^T)
    const int at_col = ((lane >> 3) & 1) << 3;
    const int bp_row = wn * 32 + (lane & 7) + ((lane >> 4) << 3);  // B (zn)
    const uint32_t bko = ((lane >> 3) & 1) * 16;

    // 2-sweep GEMM over one fp16 weight buffer into ACC[2][4][4]
#define GEMM_W(ACC, WB)                                                       \
    do {                                                                      \
        _Pragma("unroll")                                                     \
        for (int k16 = 0; k16 < 8; ++k16) {                                   \
            const int kb = k16 * 16;                                          \
            uint32_t bh[4][2], bl[4][2];                                      \
            _Pragma("unroll")                                                 \
            for (int ng = 0; ng < 2; ++ng) {                                  \
                uint32_t r4[4];                                               \
                uint32_t boff = (uint32_t)((bp_row + ng * 16) * PITB)         \
                                + kb * 2 + bko;                               \
                ldsm4(zh + boff, r4);                                         \
                bh[ng*2][0] = r4[0]; bh[ng*2][1] = r4[1];                     \
                bh[ng*2+1][0] = r4[2]; bh[ng*2+1][1] = r4[3];                 \
                ldsm4(zl + boff, r4);                                         \
                bl[ng*2][0] = r4[0]; bl[ng*2][1] = r4[1];                     \
                bl[ng*2+1][0] = r4[2]; bl[ng*2+1][1] = r4[3];                 \
            }                                                                 \
            uint32_t a4[2][4];                                                \
            _Pragma("unroll")                                                 \
            for (int mt = 0; mt < 2; ++mt) {                                  \
                uint32_t aoff = (uint32_t)((kb + at_row) * PITB) +            \
                                (wm * 32 + mt * 16 + at_col) * 2;             \
                ldsm4_t((WB) + aoff, a4[mt]);                                 \
            }                                                                 \
            _Pragma("unroll")                                                 \
            for (int mt = 0; mt < 2; ++mt)                                    \
                _Pragma("unroll")                                             \
                for (int nt = 0; nt < 4; ++nt)                                \
                    mma_f16(ACC[mt][nt], a4[mt], bh[nt]);                     \
            _Pragma("unroll")                                                 \
            for (int mt = 0; mt < 2; ++mt)                                    \
                _Pragma("unroll")                                             \
                for (int nt = 0; nt < 4; ++nt)                                \
                    mma_f16(ACC[mt][nt], a4[mt], bl[nt]);                     \
        }                                                                     \
    } while (0)

    float P[2][4][4], Q[2][4][4];
#pragma unroll
    for (int a = 0; a < 2; ++a)
#pragma unroll
        for (int b = 0; b < 4; ++b)
#pragma unroll
            for (int q = 0; q < 4; ++q) { P[a][b][q] = 0.f; Q[a][b][q] = 0.f; }

#define EPI(ph)                                                               \
    do {                                                                      \
        const float* bgp = bs + (ph) * 256;                                   \
        const float* bvp = bs + (ph) * 256 + 128;                             \
        const float* msm = bs + 640;                                          \
        __nv_bfloat16* oh = ((ph) == 0) ? g_a_hi : g_b_hi;                    \
        __nv_bfloat16* ol = ((ph) == 0) ? g_a_lo : g_b_lo;                    \
        _Pragma("unroll")                                                     \
        for (int mt = 0; mt < 2; ++mt) {                                      \
            int ch = wm * 32 + mt * 16 + (lane >> 2);                         \
            float bg0v = bgp[ch], bg1v = bgp[ch + 8];                         \
            float bv0v = bvp[ch], bv1v = bvp[ch + 8];                         \
            size_t r0 = (size_t)ch * NN + pix0;                               \
            size_t r1 = (size_t)(ch + 8) * NN + pix0;                         \
            _Pragma("unroll")                                                 \
            for (int nt = 0; nt < 4; ++nt) {                                  \
                int p = wn * 32 + nt * 8 + (lane & 3) * 2;                    \
                float m0 = msm[p], m1 = msm[p + 1];                           \
                float v00 = m0 * sigmf(P[mt][nt][0] + bg0v) * (Q[mt][nt][0] + bv0v); \
                float v01 = m1 * sigmf(P[mt][nt][1] + bg0v) * (Q[mt][nt][1] + bv0v); \
                float v10 = m0 * sigmf(P[mt][nt][2] + bg1v) * (Q[mt][nt][2] + bv1v); \
                float v11 = m1 * sigmf(P[mt][nt][3] + bg1v) * (Q[mt][nt][3] + bv1v); \
                *(uint32_t*)(oh + r0 + p) = pk_bf16x2(v00, v01);              \
                *(uint32_t*)(ol + r0 + p) = pk_bf16x2(bf16_res(v00), bf16_res(v01)); \
                *(uint32_t*)(oh + r1 + p) = pk_bf16x2(v10, v11);              \
                *(uint32_t*)(ol + r1 + p) = pk_bf16x2(bf16_res(v10), bf16_res(v11)); \
                P[mt][nt][0] = 0.f; P[mt][nt][1] = 0.f;                       \
                P[mt][nt][2] = 0.f; P[mt][nt][3] = 0.f;                       \
                Q[mt][nt][0] = 0.f; Q[mt][nt][1] = 0.f;                       \
                Q[mt][nt][2] = 0.f; Q[mt][nt][3] = 0.f;                       \
            }                                                                 \
        }                                                                     \
    } while (0)

    // ---- double-buffered schedule ----
    CP_WAIT1(); __syncthreads();        // lgate ready
    GEMM_W(P, w0A);
    __syncthreads();
    STAGE_W(2, w0A);                    // group 2: rgate
    CP_WAIT1(); __syncthreads();        // left ready
    GEMM_W(Q, w1A);
    __syncthreads();
    STAGE_W(3, w1A);                    // group 3: right
    EPI(0);                             // a epilogue (loads in flight)
    CP_WAIT1(); __syncthreads();        // rgate ready
    GEMM_W(P, w0A);
    __syncthreads();
    STAGE_W(4, w0A);                    // group 4: gate
    CP_WAIT1(); __syncthreads();        // right ready
    GEMM_W(Q, w1A);
    EPI(1);                             // b epilogue (gate load in flight)
    CP_WAIT0(); __syncthreads();        // gate ready

    // ---- phase C: g = sig(zn @ Wg + bg), C[p][ch], fp16 out ----
    {
        const int wm2 = wid & 1, wn2 = wid >> 1;   // 2 (p) x 4 (ch)
        const int a_row = wm2 * 32 + (lane & 15);
        const uint32_t ako = (lane >> 4) * 16;
        const int bt_row = (lane & 7) + (((lane >> 3) & 1) << 3);
        const int bt_col = (lane >> 4) << 3;

#pragma unroll
        for (int k16 = 0; k16 < 8; ++k16) {
            const int kb = k16 * 16;
            uint32_t bw[4][2];
#pragma unroll
            for (int ng = 0; ng < 2; ++ng) {
                uint32_t r4[4];
                uint32_t boff = (uint32_t)((kb + bt_row) * PITB) +
                                (wn2 * 32 + ng * 16 + bt_col) * 2;
                ldsm4_t(w0A + boff, r4);
                bw[ng*2][0] = r4[0]; bw[ng*2][1] = r4[1];
                bw[ng*2+1][0] = r4[2]; bw[ng*2+1][1] = r4[3];
            }
            uint32_t ah[2][4], al[2][4];
#pragma unroll
            for (int mt = 0; mt < 2; ++mt) {
                uint32_t aoff = (uint32_t)((a_row + mt * 16) * PITB) + kb * 2 + ako;
                ldsm4(zh + aoff, ah[mt]);
                ldsm4(zl + aoff, al[mt]);
            }
#pragma unroll
            for (int mt = 0; mt < 2; ++mt)
#pragma unroll
                for (int nt = 0; nt < 4; ++nt)
                    mma_f16(P[mt][nt], ah[mt], bw[nt]);
#pragma unroll
            for (int mt = 0; mt < 2; ++mt)
#pragma unroll
                for (int nt = 0; nt < 4; ++nt)
                    mma_f16(P[mt][nt], al[mt], bw[nt]);
        }

        const float* bgp = bs + 512;
#pragma unroll
        for (int mt = 0; mt < 2; ++mt) {
            int p0 = pix0 + wm2 * 32 + mt * 16 + (lane >> 2);
#pragma unroll
            for (int nt = 0; nt < 4; ++nt) {
                int ch = wn2 * 32 + nt * 8 + (lane & 3) * 2;
                float b0 = bgp[ch], b1 = bgp[ch + 1];
                __half2 v0 = __floats2half2_rn(sigmf(P[mt][nt][0] + b0),
                                               sigmf(P[mt][nt][1] + b1));
                __half2 v1 = __floats2half2_rn(sigmf(P[mt][nt][2] + b0),
                                               sigmf(P[mt][nt][3] + b1));
                *(__half2*)(g_g + (size_t)p0 * CDIM + ch) = v0;
                *(__half2*)(g_g + (size_t)(p0 + 8) * CDIM + ch) = v1;
            }
        }
    }
#undef EPI
#undef GEMM_W
#undef STAGE_W
}

// ---------------------------------------------------------------------------
// Kernel 2: per-channel X_c = A_c @ B_c^T. 256 threads, 2 CTAs/SM.
// (unchanged from round 13)
// ---------------------------------------------------------------------------
#define K2S 32768u

__global__ void __launch_bounds__(256, 2)
k2_mma()
{
    extern __shared__ char sm2[];
    const uint32_t smb = smem_u32(sm2);
    const int tid  = threadIdx.x;
    const int lane = tid & 31, wid = tid >> 5;
    const int wm = wid & 1, wn = wid >> 1;
    const int i0 = blockIdx.x * 128, j0 = blockIdx.y * 128;
    const size_t cbase = (size_t)blockIdx.z * NN;

    const __nv_bfloat16* Ah = g_a_hi + cbase + (size_t)i0 * NSEQ;
    const __nv_bfloat16* Al = g_a_lo + cbase + (size_t)i0 * NSEQ;
    const __nv_bfloat16* Bh = g_b_hi + cbase + (size_t)j0 * NSEQ;
    const __nv_bfloat16* Bl = g_b_lo + cbase + (size_t)j0 * NSEQ;

    float acc[4][4][4];
#pragma unroll
    for (int mt = 0; mt < 4; ++mt)
#pragma unroll
        for (int nt = 0; nt < 4; ++nt)
#pragma unroll
            for (int q = 0; q < 4; ++q) acc[mt][nt][q] = 0.f;

    const int arow = wm * 64 + (lane & 15);
    const int bnr  = wn * 32 + (lane & 7) + ((lane >> 4) << 3);
    const uint32_t a_koff = (uint32_t)((lane >> 4) << 4);
    const uint32_t b_koff = (uint32_t)(((lane >> 3) & 1) << 4);

#define K2_LOAD(kc, stg)                                                      \
    do {                                                                      \
        const int ke = (kc) * 32;                                             \
        _Pragma("unroll")                                                     \
        for (int t = 0; t < 2; ++t) {                                         \
            int v = tid + t * 256; int r = v >> 2, cu = v & 3;                \
            uint32_t so = SWZ64((uint32_t)(r * 64 + cu * 16));                \
            const size_t go = (size_t)r * NSEQ + ke + cu * 8;                 \
            cp16((stg) + so,           Ah + go);                              \
            cp16((stg) + 8192u + so,   Al + go);                              \
            cp16((stg) + 16384u + so,  Bh + go);                              \
            cp16((stg) + 24576u + so,  Bl + go);                              \
        }                                                                     \
        asm volatile("cp.async.commit_group;" ::: "memory");                  \
    } while (0)

    K2_LOAD(0, smb);
    K2_LOAD(1, smb + K2S);

#pragma unroll 1
    for (int kc = 0; kc < 16; ++kc) {
        if (kc < 15) asm volatile("cp.async.wait_group 1;" ::: "memory");
        else         asm volatile("cp.async.wait_group 0;" ::: "memory");
        __syncthreads();
        const uint32_t stg = smb + (uint32_t)(kc % 3) * K2S;

#pragma unroll
        for (int k16 = 0; k16 < 2; ++k16) {
            const uint32_t kbA = (uint32_t)(k16 * 32) + a_koff;
            const uint32_t kbB = (uint32_t)(k16 * 32) + b_koff;
            uint32_t bh[4][2], bl[4][2];
#pragma unroll
            for (int ng = 0; ng < 2; ++ng) {
                uint32_t r4[4];
                uint32_t off = SWZ64((uint32_t)((bnr + ng * 16) * 64) + kbB);
                ldsm4(stg + 16384u + off, r4);
                bh[ng * 2 + 0][0] = r4[0]; bh[ng * 2 + 0][1] = r4[1];
                bh[ng * 2 + 1][0] = r4[2]; bh[ng * 2 + 1][1] = r4[3];
                ldsm4(stg + 24576u + off, r4);
                bl[ng * 2 + 0][0] = r4[0]; bl[ng * 2 + 0][1] = r4[1];
                bl[ng * 2 + 1][0] = r4[2]; bl[ng * 2 + 1][1] = r4[3];
            }
            uint32_t aoff[4];
#pragma unroll
            for (int mt = 0; mt < 4; ++mt)
                aoff[mt] = SWZ64((uint32_t)((arow + mt * 16) * 64) + kbA);
            uint32_t a4[4][4];
#pragma unroll
            for (int mt = 0; mt < 4; ++mt) ldsm4(stg + aoff[mt], a4[mt]);
#pragma unroll
            for (int mt = 0; mt < 4; ++mt)
#pragma unroll
                for (int nt = 0; nt < 4; ++nt)
                    mma_bf16(acc[mt][nt], a4[mt], bh[nt]);
#pragma unroll
            for (int mt = 0; mt < 4; ++mt)
#pragma unroll
                for (int nt = 0; nt < 4; ++nt)
                    mma_bf16(acc[mt][nt], a4[mt], bl[nt]);
#pragma unroll
            for (int mt = 0; mt < 4; ++mt) ldsm4(stg + 8192u + aoff[mt], a4[mt]);
#pragma unroll
            for (int mt = 0; mt < 4; ++mt)
#pragma unroll
                for (int nt = 0; nt < 4; ++nt)
                    mma_bf16(acc[mt][nt], a4[mt], bh[nt]);
        }
        if (kc + 2 < 16) K2_LOAD(kc + 2, smb + (uint32_t)((kc + 2) % 3) * K2S);
    }

    __nv_bfloat16* Xh = g_xh + cbase + (size_t)(i0 + wm * 64) * NSEQ + j0 + wn * 32;
    __nv_bfloat16* Xl = g_xl + cbase + (size_t)(i0 + wm * 64) * NSEQ + j0 + wn * 32;
    const int rr = lane >> 2, cc = (lane & 3) * 2;
#pragma unroll
    for (int mt = 0; mt < 4; ++mt)
#pragma unroll
        for (int nt = 0; nt < 4; ++nt) {
            size_t o0 = (size_t)(mt * 16 + rr) * NSEQ + nt * 8 + cc;
            size_t o1 = o0 + 8 * NSEQ;
            float v0 = acc[mt][nt][0], v1 = acc[mt][nt][1];
            float v2 = acc[mt][nt][2], v3 = acc[mt][nt][3];
            *(uint32_t*)(Xh + o0) = pk_bf16x2(v0, v1);
            *(uint32_t*)(Xl + o0) = pk_bf16x2(bf16_res(v0), bf16_res(v1));
            *(uint32_t*)(Xh + o1) = pk_bf16x2(v2, v3);
            *(uint32_t*)(Xl + o1) = pk_bf16x2(bf16_res(v2), bf16_res(v3));
        }
#undef K2_LOAD
}

// ---------------------------------------------------------------------------
// Kernel 3: folded-LN out projection, 256 threads, 64-pixel tiles, 2 CTAs/SM.
// (round-13 version; w_out from g_wh/g_wl)
// ---------------------------------------------------------------------------
__global__ void __launch_bounds__(256, 2)
k3_mma(const float* __restrict__ b_out, float* __restrict__ out)
{
    extern __shared__ char smraw[];
    __nv_bfloat16* Xh = (__nv_bfloat16*)smraw;          // [c][p<64] pitch 72
    __nv_bfloat16* Xl = Xh + 128 * XPIT;
    __nv_bfloat16* Wh = Xl + 128 * XPIT;                // [k][n] pitch 136
    __nv_bfloat16* Wl = Wh + 128 * PIT;
    float* uS   = (float*)(Wl + 128 * PIT);
    float* wS   = uS + 128;
    float* redS = wS + 128;      // 256
    float* redQ = redS + 256;    // 256
    float* rsS  = redQ + 256;    // 64
    float* tS   = rsS + 64;      // 64

    const int tid = threadIdx.x, lane = tid & 31, wid = tid >> 5;
    const int pix0 = blockIdx.x * 64;

    {
        const uint32_t xhA = smem_u32(Xh), xlA = smem_u32(Xl);
        const uint32_t whA = smem_u32(Wh), wlA = smem_u32(Wl);
#pragma unroll
        for (int t = 0; t < 4; ++t) {
            int u = tid + t * 256;
            int c = u >> 3, q = u & 7;
            uint32_t doff = (uint32_t)(c * (XPIT * 2) + q * 16);
            size_t goff = (size_t)c * NN + pix0 + q * 8;
            cp16(xhA + doff, g_xh + goff);
            cp16(xlA + doff, g_xl + goff);
        }
#pragma unroll
        for (int t = 0; t < 8; ++t) {
            int u = tid + t * 256;
            int r = u >> 4, c = u & 15;
            uint32_t doff = (uint32_t)(r * PITB + c * 16);
            int goff = r * 128 + c * 8;
            cp16(whA + doff, g_wh + goff);
            cp16(wlA + doff, g_wl + goff);
        }
        CP_COMMIT();
    }
    if (tid < 128) { uS[tid] = g_u[tid]; wS[tid] = g_v[tid] + b_out[tid]; }
    CP_WAIT0();
    __syncthreads();

    const int p = tid & 63, quarter = tid >> 6;
    {
        float s = 0.f, ss = 0.f;
#pragma unroll 8
        for (int c = quarter * 32; c < quarter * 32 + 32; ++c) {
            float v = __bfloat162float(Xh[c * XPIT + p]) +
                      __bfloat162float(Xl[c * XPIT + p]);
            s += v; ss += v * v;
        }
        redS[tid] = s; redQ[tid] = ss;
    }
    __syncthreads();
    if (tid < 64) {
        float S  = redS[tid] + redS[tid + 64] + redS[tid + 128] + redS[tid + 192];
        float Qv = redQ[tid] + redQ[tid + 64] + redQ[tid + 128] + redQ[tid + 192];
        float mu = S * 0.0078125f;
        float rs = rsqrtf(Qv * 0.0078125f - mu * mu + 1e-5f);
        rsS[tid] = rs;
        tS[tid]  = mu * rs;
    }
    __syncthreads();

    const int wm = wid & 1, wn = wid >> 1;
    const uint32_t xh = smem_u32(Xh), xl = smem_u32(Xl);
    const uint32_t wh = smem_u32(Wh), wl = smem_u32(Wl);

    float acc[2][4][4];
#pragma unroll
    for (int a = 0; a < 2; ++a)
#pragma unroll
        for (int b = 0; b < 4; ++b)
#pragma unroll
            for (int q = 0; q < 4; ++q) acc[a][b][q] = 0.f;

    const int at_row = (lane & 7) + ((lane >> 4) << 3);
    const int at_col = ((lane >> 3) & 1) << 3;
    const int bt_row = (lane & 7) + (((lane >> 3) & 1) << 3);
    const int bt_col = (lane >> 4) << 3;

#pragma unroll
    for (int k16 = 0; k16 < 8; ++k16) {
        const int kb = k16 * 16;
        uint32_t bh[4][2], bl[4][2];
#pragma unroll
        for (int ng = 0; ng < 2; ++ng) {
            uint32_t r4[4];
            uint32_t boff = (uint32_t)((kb + bt_row) * PITB) +
                            (wn * 32 + ng * 16 + bt_col) * 2;
            ldsm4_t(wh + boff, r4);
            bh[ng*2][0] = r4[0]; bh[ng*2][1] = r4[1];
            bh[ng*2+1][0] = r4[2]; bh[ng*2+1][1] = r4[3];
            ldsm4_t(wl + boff, r4);
            bl[ng*2][0] = r4[0]; bl[ng*2][1] = r4[1];
            bl[ng*2+1][0] = r4[2]; bl[ng*2+1][1] = r4[3];
        }
        uint32_t ah[2][4], al[2][4];
#pragma unroll
        for (int mt = 0; mt < 2; ++mt) {
            uint32_t aoff = (uint32_t)((kb + at_row) * (XPIT * 2)) +
                            (wm * 32 + mt * 16 + at_col) * 2;
            ldsm4_t(xh + aoff, ah[mt]);
            ldsm4_t(xl + aoff, al[mt]);
        }
#pragma unroll
        for (int mt = 0; mt < 2; ++mt)
#pragma unroll
            for (int nt = 0; nt < 4; ++nt)
                mma_bf16(acc[mt][nt], ah[mt], bh[nt]);
#pragma unroll
        for (int mt = 0; mt < 2; ++mt)
#pragma unroll
            for (int nt = 0; nt < 4; ++nt)
                mma_bf16(acc[mt][nt], ah[mt], bl[nt]);
#pragma unroll
        for (int mt = 0; mt < 2; ++mt)
#pragma unroll
            for (int nt = 0; nt < 4; ++nt)
                mma_bf16(acc[mt][nt], al[mt], bh[nt]);
    }

#pragma unroll
    for (int mt = 0; mt < 2; ++mt) {
        int pl = wm * 32 + mt * 16 + (lane >> 2);
        int p0 = pix0 + pl;
        float rs0 = rsS[pl],     t0 = tS[pl];
        float rs1 = rsS[pl + 8], t1 = tS[pl + 8];
#pragma unroll
        for (int nt = 0; nt < 4; ++nt) {
            int ch = wn * 32 + nt * 8 + (lane & 3) * 2;
            float u0 = uS[ch], u1 = uS[ch + 1];
            float w0 = wS[ch], w1 = wS[ch + 1];
            float2 g0 = __half22float2(
                *(const __half2*)(g_g + (size_t)p0 * CDIM + ch));
            float2 g1 = __half22float2(
                *(const __half2*)(g_g + (size_t)(p0 + 8) * CDIM + ch));
            float2 v0 = make_float2((rs0 * acc[mt][nt][0] - t0 * u0 + w0) * g0.x,
                                    (rs0 * acc[mt][nt][1] - t0 * u1 + w1) * g0.y);
            float2 v1 = make_float2((rs1 * acc[mt][nt][2] - t1 * u0 + w0) * g1.x,
                                    (rs1 * acc[mt][nt][3] - t1 * u1 + w1) * g1.y);
            *(float2*)(out + (size_t)p0 * CDIM + ch) = v0;
            *(float2*)(out + (size_t)(p0 + 8) * CDIM + ch) = v1;
        }
    }
}

// ---------------------------------------------------------------------------
extern "C" void kernel_launch(void* const* d_in, const int* in_sizes, int n_in,
                              void* d_out, int out_size)
{
    const float* z        = (const float*)d_in[0];
    const float* mask     = (const float*)d_in[1];
    const float* ln_in_s  = (const float*)d_in[2];
    const float* ln_in_b  = (const float*)d_in[3];
    const float* w_left   = (const float*)d_in[4];
    const float* b_left   = (const float*)d_in[5];
    const float* w_right  = (const float*)d_in[6];
    const float* b_right  = (const float*)d_in[7];
    const float* w_lgate  = (const float*)d_in[8];
    const float* b_lgate  = (const float*)d_in[9];
    const float* w_rgate  = (const float*)d_in[10];
    const float* b_rgate  = (const float*)d_in[11];
    const float* ln_out_s = (const float*)d_in[12];
    const float* ln_out_b = (const float*)d_in[13];
    const float* w_out    = (const float*)d_in[14];
    const float* b_out    = (const float*)d_in[15];
    const float* w_gate   = (const float*)d_in[16];
    const float* b_gate   = (const float*)d_in[17];
    float* out = (float*)d_out;

    const int smem1 = (64 + 64 + 128 + 128) * PIT * 2 + 704 * 4;           // ~107 KB
    const int smem2 = 3 * (int)K2S;                                        // 98304
    const int smem3 = (2 * 128 * XPIT + 2 * 128 * PIT) * 2 +
                      (2 * 128 + 2 * 256 + 2 * 64) * 4;                    // ~110 KB

    cudaFuncSetAttribute(k1_all, cudaFuncAttributeMaxDynamicSharedMemorySize, smem1);
    cudaFuncSetAttribute(k2_mma, cudaFuncAttributeMaxDynamicSharedMemorySize, smem2);
    cudaFuncSetAttribute(k3_mma, cudaFuncAttributeMaxDynamicSharedMemorySize, smem3);

    // 0) pre-split weights (fp16 projections; w_out scaled bf16 hi/lo) + u/v
    k0_split<<<97, 256>>>(w_lgate, w_left, w_rgate, w_right, w_gate, w_out,
                          ln_out_s, ln_out_b);

    // 1) a, b, g projections from a single LN pass (2 CTAs/SM, fp16 weights)
    k1_all<<<NN / 64, 256, smem1>>>(
        z, mask, ln_in_s, ln_in_b,
        b_lgate, b_left, b_rgate, b_right, b_gate);

    // 2) triangular einsum per channel (2 CTAs/SM)
    k2_mma<<<dim3(4, 4, CDIM), 256, smem2>>>();

    // 3) folded-LN out projection + gating (2 CTAs/SM)
    k3_mma<<<NN / 64, 256, smem3>>>(b_out, out);
}

// round 17
// speedup vs baseline: 1.2973x; 1.1261x over previous
#include <cuda_runtime.h>
#include <cuda_bf16.h>
#include <cuda_fp16.h>
#include <math.h>
#include <stddef.h>
#include <stdint.h>

// Triangle multiplicative update (outgoing), N=512, cz=ch=128, fp32 in/out.
// Round 17: k2 asymmetric precision: A (a) fp16 hi/lo, B (b) single fp16,
//           2-sweep einsum. k1 writes a as fp16 hi/lo, b as single fp16.
//           k1 (r16 fp16 weights) and k3 (r13) otherwise unchanged.

#define NSEQ 512
#define CDIM 128
#define NN   (NSEQ*NSEQ)          // 262144
#define PIT  136                  // 16-bit smem pitch (elements)
#define PITB 272                  // bytes
#define XPIT 72                   // k3 X tile pitch (elements)

__device__ __half g_a_hi[(size_t)CDIM * NN];        // a hi (fp16)
__device__ __half g_a_lo[(size_t)CDIM * NN];        // a lo (fp16 residual)
__device__ __half g_b[(size_t)CDIM * NN];           // b (single fp16)
__device__ __half g_g[(size_t)NN * CDIM];           // g[pix][c] fp16
__device__ __nv_bfloat16 g_xh[(size_t)CDIM * NN];   // x hi [c][i][j]
__device__ __nv_bfloat16 g_xl[(size_t)CDIM * NN];   // x lo
// fp16 projection weights: 0=lgate 1=left 2=rgate 3=right 4=gate
__device__ __align__(16) __half g_wf[5 * 16384];
// bf16 hi/lo scaled w_out (for k3)
__device__ __align__(16) __nv_bfloat16 g_wh[16384];
__device__ __align__(16) __nv_bfloat16 g_wl[16384];
__device__ float g_u[128];   // sum_c s[c]*w_out[c][n]
__device__ float g_v[128];   // sum_c b_ln[c]*w_out[c][n]

__device__ __forceinline__ float sigmf(float x) {
    return 1.0f / (1.0f + __expf(-x));
}
__device__ __forceinline__ unsigned pk_bf16x2(float a, float b) {
    __nv_bfloat162 t = __floats2bfloat162_rn(a, b);
    return *reinterpret_cast<unsigned*>(&t);
}
__device__ __forceinline__ float bf16_res(float v) {   // v - bf16(v)
    return v - __bfloat162float(__float2bfloat16(v));
}
__device__ __forceinline__ float f16_res(float v) {    // v - fp16(v)
    return v - __half2float(__float2half_rn(v));
}
__device__ __forceinline__ uint32_t smem_u32(const void* p) {
    uint32_t a;
    asm("{ .reg .u64 t; cvta.to.shared.u64 t, %1; cvt.u32.u64 %0, t; }"
        : "=r"(a) : "l"(p));
    return a;
}
__device__ __forceinline__ void cp16(uint32_t dst, const void* src) {
    asm volatile("cp.async.cg.shared.global [%0], [%1], 16;"
                 :: "r"(dst), "l"(src) : "memory");
}
#define CP_COMMIT() asm volatile("cp.async.commit_group;" ::: "memory")
#define CP_WAIT0()  asm volatile("cp.async.wait_group 0;" ::: "memory")
#define CP_WAIT1()  asm volatile("cp.async.wait_group 1;" ::: "memory")
#define SWZ(o)   ((o) ^ (((o) >> 3) & 0x70))
#define SWZ64(o) ((o) ^ (((o) >> 3) & 0x30))

__device__ __forceinline__ void ldsm4(uint32_t addr, uint32_t* r) {
    asm volatile("ldmatrix.sync.aligned.m8n8.x4.shared.b16 {%0,%1,%2,%3}, [%4];"
                 : "=r"(r[0]), "=r"(r[1]), "=r"(r[2]), "=r"(r[3]) : "r"(addr));
}
__device__ __forceinline__ void ldsm4_t(uint32_t addr, uint32_t* r) {
    asm volatile("ldmatrix.sync.aligned.m8n8.x4.trans.shared.b16 {%0,%1,%2,%3}, [%4];"
                 : "=r"(r[0]), "=r"(r[1]), "=r"(r[2]), "=r"(r[3]) : "r"(addr));
}
__device__ __forceinline__ void mma_bf16(float* c, const uint32_t* a,
                                         const uint32_t* b) {
    asm volatile(
        "mma.sync.aligned.m16n8k16.row.col.f32.bf16.bf16.f32 "
        "{%0,%1,%2,%3}, {%4,%5,%6,%7}, {%8,%9}, {%0,%1,%2,%3};"
        : "+f"(c[0]), "+f"(c[1]), "+f"(c[2]), "+f"(c[3])
        : "r"(a[0]), "r"(a[1]), "r"(a[2]), "r"(a[3]), "r"(b[0]), "r"(b[1]));
}
__device__ __forceinline__ void mma_f16(float* c, const uint32_t* a,
                                        const uint32_t* b) {
    asm volatile(
        "mma.sync.aligned.m16n8k16.row.col.f32.f16.f16.f32 "
        "{%0,%1,%2,%3}, {%4,%5,%6,%7}, {%8,%9}, {%0,%1,%2,%3};"
        : "+f"(c[0]), "+f"(c[1]), "+f"(c[2]), "+f"(c[3])
        : "r"(a[0]), "r"(a[1]), "r"(a[2]), "r"(a[3]), "r"(b[0]), "r"(b[1]));
}

__device__ __forceinline__ void split4(float4 v, uint2& hv, uint2& lv) {
    hv.x = pk_bf16x2(v.x, v.y);
    hv.y = pk_bf16x2(v.z, v.w);
    lv.x = pk_bf16x2(bf16_res(v.x), bf16_res(v.y));
    lv.y = pk_bf16x2(bf16_res(v.z), bf16_res(v.w));
}
__device__ __forceinline__ unsigned pk_h2(float a, float b) {
    __half2 t = __floats2half2_rn(a, b);
    return *reinterpret_cast<unsigned*>(&t);
}
__device__ __forceinline__ void split4h(float4 v, uint2& hv, uint2& lv) {
    hv.x = pk_h2(v.x, v.y);
    hv.y = pk_h2(v.z, v.w);
    lv.x = pk_h2(f16_res(v.x), f16_res(v.y));
    lv.y = pk_h2(f16_res(v.z), f16_res(v.w));
}

// ---------------------------------------------------------------------------
// Kernel 0: 5 projection weights -> fp16; w_out (scaled) -> bf16 hi/lo; u/v.
// ---------------------------------------------------------------------------
__global__ void __launch_bounds__(256)
k0_split(const float* __restrict__ w0, const float* __restrict__ w1,
         const float* __restrict__ w2, const float* __restrict__ w3,
         const float* __restrict__ w4, const float* __restrict__ w5,
         const float* __restrict__ so, const float* __restrict__ bo)
{
    if (blockIdx.x == 96) {
        int n = threadIdx.x;
        if (n < 128) {
            float u = 0.f, v = 0.f;
            for (int c = 0; c < 128; ++c) {
                float w = w5[c * 128 + n];
                u += so[c] * w;
                v += bo[c] * w;
            }
            g_u[n] = u; g_v[n] = v;
        }
        return;
    }
    const float* ws[6] = {w0, w1, w2, w3, w4, w5};
    int idx = blockIdx.x * 256 + threadIdx.x;
    int m = idx >> 12;
    int e = (idx & 4095) * 4;
    float4 v = *(const float4*)(ws[m] + e);
    if (m < 5) {
        __half2 h0 = __floats2half2_rn(v.x, v.y);
        __half2 h1 = __floats2half2_rn(v.z, v.w);
        *(__half2*)(g_wf + m * 16384 + e)     = h0;
        *(__half2*)(g_wf + m * 16384 + e + 2) = h1;
    } else {
        float sc = so[e >> 7];
        v.x *= sc; v.y *= sc; v.z *= sc; v.w *= sc;
        uint2 hv, lv;
        split4(v, hv, lv);
        *(uint2*)(g_wh + e) = hv;
        *(uint2*)(g_wl + e) = lv;
    }
}

// ---------------------------------------------------------------------------
// Kernel 1: 256 threads, 64-pixel tiles, 2 CTAs/SM.
// fp16 weights (single), fp16 hi/lo zn, 2-sweep GEMMs, double-buffered W.
// a written fp16 hi/lo; b written single fp16.
// ---------------------------------------------------------------------------
__global__ void __launch_bounds__(256, 2)
k1_all(const float* __restrict__ z, const float* __restrict__ mask,
       const float* __restrict__ ln_s, const float* __restrict__ ln_b,
       const float* __restrict__ b_lg, const float* __restrict__ b_l,
       const float* __restrict__ b_rg, const float* __restrict__ b_r,
       const float* __restrict__ b_g)
{
    extern __shared__ char smraw[];
    __half* znh = (__half*)smraw;                 // [p<64][k] pitch 136
    __half* znl = znh + 64 * PIT;
    __half* W0  = znl + 64 * PIT;                 // [k][n] pitch 136
    __half* W1  = W0 + 128 * PIT;
    float* bs = (float*)(W1 + 128 * PIT);
    // bs: [0)lg [128)l [256)rg [384)r [512)g [640)mask(64)

    const int tid = threadIdx.x, lane = tid & 31, wid = tid >> 5;
    const int pix0 = blockIdx.x * 64;

    const uint32_t w0A = smem_u32(W0), w1A = smem_u32(W1);
    const uint32_t zh = smem_u32(znh), zl = smem_u32(znl);

#define STAGE_W(mi, dstA)                                                     \
    do {                                                                      \
        const __half* S = g_wf + (mi) * 16384;                                \
        _Pragma("unroll")                                                     \
        for (int t = 0; t < 8; ++t) {                                         \
            int u = tid + t * 256;                                            \
            int r = u >> 4, c = u & 15;                                       \
            uint32_t doff = (uint32_t)(r * PITB + c * 16);                    \
            int goff = r * 128 + c * 8;                                       \
            cp16((dstA) + doff, S + goff);                                    \
        }                                                                     \
        CP_COMMIT();                                                          \
    } while (0)

    STAGE_W(0, w0A);   // group 0: lgate
    STAGE_W(1, w1A);   // group 1: left

    bs[tid]       = (tid < 128) ? b_lg[tid] : b_l[tid - 128];
    bs[256 + tid] = (tid < 128) ? b_rg[tid] : b_r[tid - 128];
    if (tid < 128) bs[512 + tid] = b_g[tid];
    if (tid < 64)  bs[640 + tid] = mask[pix0 + tid];

    // LayerNorm: 8 warps, 8 rows each (overlaps with weight cp.async)
    {
        float4 s4 = ((const float4*)ln_s)[lane];
        float4 b4 = ((const float4*)ln_b)[lane];
        float4 v[8];
#pragma unroll
        for (int t = 0; t < 8; ++t)
            v[t] = ((const float4*)(z + (size_t)(pix0 + t * 8 + wid) * CDIM))[lane];
#pragma unroll
        for (int t = 0; t < 8; ++t) {
            int r = t * 8 + wid;
            float s  = v[t].x + v[t].y + v[t].z + v[t].w;
            float ss = v[t].x*v[t].x + v[t].y*v[t].y + v[t].z*v[t].z + v[t].w*v[t].w;
#pragma unroll
            for (int o = 16; o > 0; o >>= 1) {
                s  += __shfl_xor_sync(0xffffffffu, s,  o);
                ss += __shfl_xor_sync(0xffffffffu, ss, o);
            }
            float mu   = s * 0.0078125f;
            float rstd = rsqrtf(ss * 0.0078125f - mu * mu + 1e-5f);
            float4 o4;
            o4.x = (v[t].x - mu) * rstd * s4.x + b4.x;
            o4.y = (v[t].y - mu) * rstd * s4.y + b4.y;
            o4.z = (v[t].z - mu) * rstd * s4.z + b4.z;
            o4.w = (v[t].w - mu) * rstd * s4.w + b4.w;
            uint2 hv, lv;
            split4h(o4, hv, lv);
            *(uint2*)(&znh[r * PIT + lane * 4]) = hv;
            *(uint2*)(&znl[r * PIT + lane * 4]) = lv;
        }
    }

    // gated warp grid: wm (ch) in [0,4), wn (p) in [0,2)
    const int wm = wid & 3, wn = wid >> 2;
    const int at_row = (lane & 7) + ((lane >> 4) << 3);      // trans A (W^T)
    const int at_col = ((lane >> 3) & 1) << 3;
    const int bp_row = wn * 32 + (lane & 7) + ((lane >> 4) << 3);  // B (zn)
    const uint32_t bko = ((lane >> 3) & 1) * 16;

#define GEMM_W(ACC, WB)                                                       \
    do {                                                                      \
        _Pragma("unroll")                                                     \
        for (int k16 = 0; k16 < 8; ++k16) {                                   \
            const int kb = k16 * 16;                                          \
            uint32_t bh[4][2], bl[4][2];                                      \
            _Pragma("unroll")                                                 \
            for (int ng = 0; ng < 2; ++ng) {                                  \
                uint32_t r4[4];                                               \
                uint32_t boff = (uint32_t)((bp_row + ng * 16) * PITB)         \
                                + kb * 2 + bko;                               \
                ldsm4(zh + boff, r4);                                         \
                bh[ng*2][0] = r4[0]; bh[ng*2][1] = r4[1];                     \
                bh[ng*2+1][0] = r4[2]; bh[ng*2+1][1] = r4[3];                 \
                ldsm4(zl + boff, r4);                                         \
                bl[ng*2][0] = r4[0]; bl[ng*2][1] = r4[1];                     \
                bl[ng*2+1][0] = r4[2]; bl[ng*2+1][1] = r4[3];                 \
            }                                                                 \
            uint32_t a4[2][4];                                                \
            _Pragma("unroll")                                                 \
            for (int mt = 0; mt < 2; ++mt) {                                  \
                uint32_t aoff = (uint32_t)((kb + at_row) * PITB) +            \
                                (wm * 32 + mt * 16 + at_col) * 2;             \
                ldsm4_t((WB) + aoff, a4[mt]);                                 \
            }                                                                 \
            _Pragma("unroll")                                                 \
            for (int mt = 0; mt < 2; ++mt)                                    \
                _Pragma("unroll")                                             \
                for (int nt = 0; nt < 4; ++nt)                                \
                    mma_f16(ACC[mt][nt], a4[mt], bh[nt]);                     \
            _Pragma("unroll")                                                 \
            for (int mt = 0; mt < 2; ++mt)                                    \
                _Pragma("unroll")                                             \
                for (int nt = 0; nt < 4; ++nt)                                \
                    mma_f16(ACC[mt][nt], a4[mt], bl[nt]);                     \
        }                                                                     \
    } while (0)

    float P[2][4][4], Q[2][4][4];
#pragma unroll
    for (int a = 0; a < 2; ++a)
#pragma unroll
        for (int b = 0; b < 4; ++b)
#pragma unroll
            for (int q = 0; q < 4; ++q) { P[a][b][q] = 0.f; Q[a][b][q] = 0.f; }

    // epilogue: ph==0 -> a (fp16 hi/lo); ph==1 -> b (single fp16)
#define EPI(ph)                                                               \
    do {                                                                      \
        const float* bgp = bs + (ph) * 256;                                   \
        const float* bvp = bs + (ph) * 256 + 128;                             \
        const float* msm = bs + 640;                                          \
        _Pragma("unroll")                                                     \
        for (int mt = 0; mt < 2; ++mt) {                                      \
            int ch = wm * 32 + mt * 16 + (lane >> 2);                         \
            float bg0v = bgp[ch], bg1v = bgp[ch + 8];                         \
            float bv0v = bvp[ch], bv1v = bvp[ch + 8];                         \
            size_t r0 = (size_t)ch * NN + pix0;                               \
            size_t r1 = (size_t)(ch + 8) * NN + pix0;                         \
            _Pragma("unroll")                                                 \
            for (int nt = 0; nt < 4; ++nt) {                                  \
                int p = wn * 32 + nt * 8 + (lane & 3) * 2;                    \
                float m0 = msm[p], m1 = msm[p + 1];                           \
                float v00 = m0 * sigmf(P[mt][nt][0] + bg0v) * (Q[mt][nt][0] + bv0v); \
                float v01 = m1 * sigmf(P[mt][nt][1] + bg0v) * (Q[mt][nt][1] + bv0v); \
                float v10 = m0 * sigmf(P[mt][nt][2] + bg1v) * (Q[mt][nt][2] + bv1v); \
                float v11 = m1 * sigmf(P[mt][nt][3] + bg1v) * (Q[mt][nt][3] + bv1v); \
                if ((ph) == 0) {                                              \
                    *(uint32_t*)(g_a_hi + r0 + p) = pk_h2(v00, v01);          \
                    *(uint32_t*)(g_a_lo + r0 + p) = pk_h2(f16_res(v00), f16_res(v01)); \
                    *(uint32_t*)(g_a_hi + r1 + p) = pk_h2(v10, v11);          \
                    *(uint32_t*)(g_a_lo + r1 + p) = pk_h2(f16_res(v10), f16_res(v11)); \
                } else {                                                      \
                    *(uint32_t*)(g_b + r0 + p) = pk_h2(v00, v01);             \
                    *(uint32_t*)(g_b + r1 + p) = pk_h2(v10, v11);             \
                }                                                             \
                P[mt][nt][0] = 0.f; P[mt][nt][1] = 0.f;                       \
                P[mt][nt][2] = 0.f; P[mt][nt][3] = 0.f;                       \
                Q[mt][nt][0] = 0.f; Q[mt][nt][1] = 0.f;                       \
                Q[mt][nt][2] = 0.f; Q[mt][nt][3] = 0.f;                       \
            }                                                                 \
        }                                                                     \
    } while (0)

    // ---- double-buffered schedule ----
    CP_WAIT1(); __syncthreads();        // lgate ready
    GEMM_W(P, w0A);
    __syncthreads();
    STAGE_W(2, w0A);                    // group 2: rgate
    CP_WAIT1(); __syncthreads();        // left ready
    GEMM_W(Q, w1A);
    __syncthreads();
    STAGE_W(3, w1A);                    // group 3: right
    EPI(0);                             // a epilogue (loads in flight)
    CP_WAIT1(); __syncthreads();        // rgate ready
    GEMM_W(P, w0A);
    __syncthreads();
    STAGE_W(4, w0A);                    // group 4: gate
    CP_WAIT1(); __syncthreads();        // right ready
    GEMM_W(Q, w1A);
    EPI(1);                             // b epilogue (gate load in flight)
    CP_WAIT0(); __syncthreads();        // gate ready

    // ---- phase C: g = sig(zn @ Wg + bg), C[p][ch], fp16 out ----
    {
        const int wm2 = wid & 1, wn2 = wid >> 1;   // 2 (p) x 4 (ch)
        const int a_row = wm2 * 32 + (lane & 15);
        const uint32_t ako = (lane >> 4) * 16;
        const int bt_row = (lane & 7) + (((lane >> 3) & 1) << 3);
        const int bt_col = (lane >> 4) << 3;

#pragma unroll
        for (int k16 = 0; k16 < 8; ++k16) {
            const int kb = k16 * 16;
            uint32_t bw[4][2];
#pragma unroll
            for (int ng = 0; ng < 2; ++ng) {
                uint32_t r4[4];
                uint32_t boff = (uint32_t)((kb + bt_row) * PITB) +
                                (wn2 * 32 + ng * 16 + bt_col) * 2;
                ldsm4_t(w0A + boff, r4);
                bw[ng*2][0] = r4[0]; bw[ng*2][1] = r4[1];
                bw[ng*2+1][0] = r4[2]; bw[ng*2+1][1] = r4[3];
            }
            uint32_t ah[2][4], al[2][4];
#pragma unroll
            for (int mt = 0; mt < 2; ++mt) {
                uint32_t aoff = (uint32_t)((a_row + mt * 16) * PITB) + kb * 2 + ako;
                ldsm4(zh + aoff, ah[mt]);
                ldsm4(zl + aoff, al[mt]);
            }
#pragma unroll
            for (int mt = 0; mt < 2; ++mt)
#pragma unroll
                for (int nt = 0; nt < 4; ++nt)
                    mma_f16(P[mt][nt], ah[mt], bw[nt]);
#pragma unroll
            for (int mt = 0; mt < 2; ++mt)
#pragma unroll
                for (int nt = 0; nt < 4; ++nt)
                    mma_f16(P[mt][nt], al[mt], bw[nt]);
        }

        const float* bgp = bs + 512;
#pragma unroll
        for (int mt = 0; mt < 2; ++mt) {
            int p0 = pix0 + wm2 * 32 + mt * 16 + (lane >> 2);
#pragma unroll
            for (int nt = 0; nt < 4; ++nt) {
                int ch = wn2 * 32 + nt * 8 + (lane & 3) * 2;
                float b0 = bgp[ch], b1 = bgp[ch + 1];
                __half2 v0 = __floats2half2_rn(sigmf(P[mt][nt][0] + b0),
                                               sigmf(P[mt][nt][1] + b1));
                __half2 v1 = __floats2half2_rn(sigmf(P[mt][nt][2] + b0),
                                               sigmf(P[mt][nt][3] + b1));
                *(__half2*)(g_g + (size_t)p0 * CDIM + ch) = v0;
                *(__half2*)(g_g + (size_t)(p0 + 8) * CDIM + ch) = v1;
            }
        }
    }
#undef EPI
#undef GEMM_W
#undef STAGE_W
}

// ---------------------------------------------------------------------------
// Kernel 2: per-channel X_c = A_c @ B_c^T. 256 threads, 2 CTAs/SM.
// A fp16 hi/lo, B single fp16 -> 2 sweeps. Stage 24KB x 3.
// ---------------------------------------------------------------------------
#define K2S 24576u

__global__ void __launch_bounds__(256, 2)
k2_mma()
{
    extern __shared__ char sm2[];
    const uint32_t smb = smem_u32(sm2);
    const int tid  = threadIdx.x;
    const int lane = tid & 31, wid = tid >> 5;
    const int wm = wid & 1, wn = wid >> 1;
    const int i0 = blockIdx.x * 128, j0 = blockIdx.y * 128;
    const size_t cbase = (size_t)blockIdx.z * NN;

    const __half* Ah = g_a_hi + cbase + (size_t)i0 * NSEQ;
    const __half* Al = g_a_lo + cbase + (size_t)i0 * NSEQ;
    const __half* Bp = g_b    + cbase + (size_t)j0 * NSEQ;

    float acc[4][4][4];
#pragma unroll
    for (int mt = 0; mt < 4; ++mt)
#pragma unroll
        for (int nt = 0; nt < 4; ++nt)
#pragma unroll
            for (int q = 0; q < 4; ++q) acc[mt][nt][q] = 0.f;

    const int arow = wm * 64 + (lane & 15);
    const int bnr  = wn * 32 + (lane & 7) + ((lane >> 4) << 3);
    const uint32_t a_koff = (uint32_t)((lane >> 4) << 4);
    const uint32_t b_koff = (uint32_t)(((lane >> 3) & 1) << 4);

    // stage: [Ah 8K][Al 8K][B 8K], rows of 64B, SW64 swizzle
#define K2_LOAD(kc, stg)                                                      \
    do {                                                                      \
        const int ke = (kc) * 32;                                             \
        _Pragma("unroll")                                                     \
        for (int t = 0; t < 2; ++t) {                                         \
            int v = tid + t * 256; int r = v >> 2, cu = v & 3;                \
            uint32_t so = SWZ64((uint32_t)(r * 64 + cu * 16));                \
            const size_t go = (size_t)r * NSEQ + ke + cu * 8;                 \
            cp16((stg) + so,           Ah + go);                              \
            cp16((stg) + 8192u + so,   Al + go);                              \
            cp16((stg) + 16384u + so,  Bp + go);                              \
        }                                                                     \
        asm volatile("cp.async.commit_group;" ::: "memory");                  \
    } while (0)

    K2_LOAD(0, smb);
    K2_LOAD(1, smb + K2S);

#pragma unroll 1
    for (int kc = 0; kc < 16; ++kc) {
        if (kc < 15) asm volatile("cp.async.wait_group 1;" ::: "memory");
        else         asm volatile("cp.async.wait_group 0;" ::: "memory");
        __syncthreads();
        const uint32_t stg = smb + (uint32_t)(kc % 3) * K2S;

#pragma unroll
        for (int k16 = 0; k16 < 2; ++k16) {
            const uint32_t kbA = (uint32_t)(k16 * 32) + a_koff;
            const uint32_t kbB = (uint32_t)(k16 * 32) + b_koff;
            uint32_t bw[4][2];
#pragma unroll
            for (int ng = 0; ng < 2; ++ng) {
                uint32_t r4[4];
                uint32_t off = SWZ64((uint32_t)((bnr + ng * 16) * 64) + kbB);
                ldsm4(stg + 16384u + off, r4);
                bw[ng * 2 + 0][0] = r4[0]; bw[ng * 2 + 0][1] = r4[1];
                bw[ng * 2 + 1][0] = r4[2]; bw[ng * 2 + 1][1] = r4[3];
            }
            uint32_t aoff[4];
#pragma unroll
            for (int mt = 0; mt < 4; ++mt)
                aoff[mt] = SWZ64((uint32_t)((arow + mt * 16) * 64) + kbA);
            uint32_t a4[4][4];
            // sweep 1: Ah x B
#pragma unroll
            for (int mt = 0; mt < 4; ++mt) ldsm4(stg + aoff[mt], a4[mt]);
#pragma unroll
            for (int mt = 0; mt < 4; ++mt)
#pragma unroll
                for (int nt = 0; nt < 4; ++nt)
                    mma_f16(acc[mt][nt], a4[mt], bw[nt]);
            // sweep 2: Al x B
#pragma unroll
            for (int mt = 0; mt < 4; ++mt) ldsm4(stg + 8192u + aoff[mt], a4[mt]);
#pragma unroll
            for (int mt = 0; mt < 4; ++mt)
#pragma unroll
                for (int nt = 0; nt < 4; ++nt)
                    mma_f16(acc[mt][nt], a4[mt], bw[nt]);
        }
        if (kc + 2 < 16) K2_LOAD(kc + 2, smb + (uint32_t)((kc + 2) % 3) * K2S);
    }

    // epilogue: split to bf16 hi/lo -> g_xh/g_xl [c][i][j]
    __nv_bfloat16* Xh = g_xh + cbase + (size_t)(i0 + wm * 64) * NSEQ + j0 + wn * 32;
    __nv_bfloat16* Xl = g_xl + cbase + (size_t)(i0 + wm * 64) * NSEQ + j0 + wn * 32;
    const int rr = lane >> 2, cc = (lane & 3) * 2;
#pragma unroll
    for (int mt = 0; mt < 4; ++mt)
#pragma unroll
        for (int nt = 0; nt < 4; ++nt) {
            size_t o0 = (size_t)(mt * 16 + rr) * NSEQ + nt * 8 + cc;
            size_t o1 = o0 + 8 * NSEQ;
            float v0 = acc[mt][nt][0], v1 = acc[mt][nt][1];
            float v2 = acc[mt][nt][2], v3 = acc[mt][nt][3];
            *(uint32_t*)(Xh + o0) = pk_bf16x2(v0, v1);
            *(uint32_t*)(Xl + o0) = pk_bf16x2(bf16_res(v0), bf16_res(v1));
            *(uint32_t*)(Xh + o1) = pk_bf16x2(v2, v3);
            *(uint32_t*)(Xl + o1) = pk_bf16x2(bf16_res(v2), bf16_res(v3));
        }
#undef K2_LOAD
}

// ---------------------------------------------------------------------------
// Kernel 3: folded-LN out projection, 256 threads, 64-pixel tiles, 2 CTAs/SM.
// (round-13 version; w_out from g_wh/g_wl)
// ---------------------------------------------------------------------------
__global__ void __launch_bounds__(256, 2)
k3_mma(const float* __restrict__ b_out, float* __restrict__ out)
{
    extern __shared__ char smraw[];
    __nv_bfloat16* Xh = (__nv_bfloat16*)smraw;          // [c][p<64] pitch 72
    __nv_bfloat16* Xl = Xh + 128 * XPIT;
    __nv_bfloat16* Wh = Xl + 128 * XPIT;                // [k][n] pitch 136
    __nv_bfloat16* Wl = Wh + 128 * PIT;
    float* uS   = (float*)(Wl + 128 * PIT);
    float* wS   = uS + 128;
    float* redS = wS + 128;      // 256
    float* redQ = redS + 256;    // 256
    float* rsS  = redQ + 256;    // 64
    float* tS   = rsS + 64;      // 64

    const int tid = threadIdx.x, lane = tid & 31, wid = tid >> 5;
    const int pix0 = blockIdx.x * 64;

    {
        const uint32_t xhA = smem_u32(Xh), xlA = smem_u32(Xl);
        const uint32_t whA = smem_u32(Wh), wlA = smem_u32(Wl);
#pragma unroll
        for (int t = 0; t < 4; ++t) {
            int u = tid + t * 256;
            int c = u >> 3, q = u & 7;
            uint32_t doff = (uint32_t)(c * (XPIT * 2) + q * 16);
            size_t goff = (size_t)c * NN + pix0 + q * 8;
            cp16(xhA + doff, g_xh + goff);
            cp16(xlA + doff, g_xl + goff);
        }
#pragma unroll
        for (int t = 0; t < 8; ++t) {
            int u = tid + t * 256;
            int r = u >> 4, c = u & 15;
            uint32_t doff = (uint32_t)(r * PITB + c * 16);
            int goff = r * 128 + c * 8;
            cp16(whA + doff, g_wh + goff);
            cp16(wlA + doff, g_wl + goff);
        }
        CP_COMMIT();
    }
    if (tid < 128) { uS[tid] = g_u[tid]; wS[tid] = g_v[tid] + b_out[tid]; }
    CP_WAIT0();
    __syncthreads();

    const int p = tid & 63, quarter = tid >> 6;
    {
        float s = 0.f, ss = 0.f;
#pragma unroll 8
        for (int c = quarter * 32; c < quarter * 32 + 32; ++c) {
            float v = __bfloat162float(Xh[c * XPIT + p]) +
                      __bfloat162float(Xl[c * XPIT + p]);
            s += v; ss += v * v;
        }
        redS[tid] = s; redQ[tid] = ss;
    }
    __syncthreads();
    if (tid < 64) {
        float S  = redS[tid] + redS[tid + 64] + redS[tid + 128] + redS[tid + 192];
        float Qv = redQ[tid] + redQ[tid + 64] + redQ[tid + 128] + redQ[tid + 192];
        float mu = S * 0.0078125f;
        float rs = rsqrtf(Qv * 0.0078125f - mu * mu + 1e-5f);
        rsS[tid] = rs;
        tS[tid]  = mu * rs;
    }
    __syncthreads();

    const int wm = wid & 1, wn = wid >> 1;
    const uint32_t xh = smem_u32(Xh), xl = smem_u32(Xl);
    const uint32_t wh = smem_u32(Wh), wl = smem_u32(Wl);

    float acc[2][4][4];
#pragma unroll
    for (int a = 0; a < 2; ++a)
#pragma unroll
        for (int b = 0; b < 4; ++b)
#pragma unroll
            for (int q = 0; q < 4; ++q) acc[a][b][q] = 0.f;

    const int at_row = (lane & 7) + ((lane >> 4) << 3);
    const int at_col = ((lane >> 3) & 1) << 3;
    const int bt_row = (lane & 7) + (((lane >> 3) & 1) << 3);
    const int bt_col = (lane >> 4) << 3;

#pragma unroll
    for (int k16 = 0; k16 < 8; ++k16) {
        const int kb = k16 * 16;
        uint32_t bh[4][2], bl[4][2];
#pragma unroll
        for (int ng = 0; ng < 2; ++ng) {
            uint32_t r4[4];
            uint32_t boff = (uint32_t)((kb + bt_row) * PITB) +
                            (wn * 32 + ng * 16 + bt_col) * 2;
            ldsm4_t(wh + boff, r4);
            bh[ng*2][0] = r4[0]; bh[ng*2][1] = r4[1];
            bh[ng*2+1][0] = r4[2]; bh[ng*2+1][1] = r4[3];
            ldsm4_t(wl + boff, r4);
            bl[ng*2][0] = r4[0]; bl[ng*2][1] = r4[1];
            bl[ng*2+1][0] = r4[2]; bl[ng*2+1][1] = r4[3];
        }
        uint32_t ah[2][4], al[2][4];
#pragma unroll
        for (int mt = 0; mt < 2; ++mt) {
            uint32_t aoff = (uint32_t)((kb + at_row) * (XPIT * 2)) +
                            (wm * 32 + mt * 16 + at_col) * 2;
            ldsm4_t(xh + aoff, ah[mt]);
            ldsm4_t(xl + aoff, al[mt]);
        }
#pragma unroll
        for (int mt = 0; mt < 2; ++mt)
#pragma unroll
            for (int nt = 0; nt < 4; ++nt)
                mma_bf16(acc[mt][nt], ah[mt], bh[nt]);
#pragma unroll
        for (int mt = 0; mt < 2; ++mt)
#pragma unroll
            for (int nt = 0; nt < 4; ++nt)
                mma_bf16(acc[mt][nt], ah[mt], bl[nt]);
#pragma unroll
        for (int mt = 0; mt < 2; ++mt)
#pragma unroll
            for (int nt = 0; nt < 4; ++nt)
                mma_bf16(acc[mt][nt], al[mt], bh[nt]);
    }

#pragma unroll
    for (int mt = 0; mt < 2; ++mt) {
        int pl = wm * 32 + mt * 16 + (lane >> 2);
        int p0 = pix0 + pl;
        float rs0 = rsS[pl],     t0 = tS[pl];
        float rs1 = rsS[pl + 8], t1 = tS[pl + 8];
#pragma unroll
        for (int nt = 0; nt < 4; ++nt) {
            int ch = wn * 32 + nt * 8 + (lane & 3) * 2;
            float u0 = uS[ch], u1 = uS[ch + 1];
            float w0 = wS[ch], w1 = wS[ch + 1];
            float2 g0 = __half22float2(
                *(const __half2*)(g_g + (size_t)p0 * CDIM + ch));
            float2 g1 = __half22float2(
                *(const __half2*)(g_g + (size_t)(p0 + 8) * CDIM + ch));
            float2 v0 = make_float2((rs0 * acc[mt][nt][0] - t0 * u0 + w0) * g0.x,
                                    (rs0 * acc[mt][nt][1] - t0 * u1 + w1) * g0.y);
            float2 v1 = make_float2((rs1 * acc[mt][nt][2] - t1 * u0 + w0) * g1.x,
                                    (rs1 * acc[mt][nt][3] - t1 * u1 + w1) * g1.y);
            *(float2*)(out + (size_t)p0 * CDIM + ch) = v0;
            *(float2*)(out + (size_t)(p0 + 8) * CDIM + ch) = v1;
        }
    }
}

// ---------------------------------------------------------------------------
extern "C" void kernel_launch(void* const* d_in, const int* in_sizes, int n_in,
                              void* d_out, int out_size)
{
    const float* z        = (const float*)d_in[0];
    const float* mask     = (const float*)d_in[1];
    const float* ln_in_s  = (const float*)d_in[2];
    const float* ln_in_b  = (const float*)d_in[3];
    const float* w_left   = (const float*)d_in[4];
    const float* b_left   = (const float*)d_in[5];
    const float* w_right  = (const float*)d_in[6];
    const float* b_right  = (const float*)d_in[7];
    const float* w_lgate  = (const float*)d_in[8];
    const float* b_lgate  = (const float*)d_in[9];
    const float* w_rgate  = (const float*)d_in[10];
    const float* b_rgate  = (const float*)d_in[11];
    const float* ln_out_s = (const float*)d_in[12];
    const float* ln_out_b = (const float*)d_in[13];
    const float* w_out    = (const float*)d_in[14];
    const float* b_out    = (const float*)d_in[15];
    const float* w_gate   = (const float*)d_in[16];
    const float* b_gate   = (const float*)d_in[17];
    float* out = (float*)d_out;

    const int smem1 = (64 + 64 + 128 + 128) * PIT * 2 + 704 * 4;           // ~107 KB
    const int smem2 = 3 * (int)K2S;                                        // 73728
    const int smem3 = (2 * 128 * XPIT + 2 * 128 * PIT) * 2 +
                      (2 * 128 + 2 * 256 + 2 * 64) * 4;                    // ~110 KB

    cudaFuncSetAttribute(k1_all, cudaFuncAttributeMaxDynamicSharedMemorySize, smem1);
    cudaFuncSetAttribute(k2_mma, cudaFuncAttributeMaxDynamicSharedMemorySize, smem2);
    cudaFuncSetAttribute(k3_mma, cudaFuncAttributeMaxDynamicSharedMemorySize, smem3);

    // 0) pre-split weights (fp16 projections; w_out scaled bf16 hi/lo) + u/v
    k0_split<<<97, 256>>>(w_lgate, w_left, w_rgate, w_right, w_gate, w_out,
                          ln_out_s, ln_out_b);

    // 1) a, b, g projections from a single LN pass (2 CTAs/SM, fp16 weights)
    k1_all<<<NN / 64, 256, smem1>>>(
        z, mask, ln_in_s, ln_in_b,
        b_lgate, b_left, b_rgate, b_right, b_gate);

    // 2) triangular einsum per channel (2 CTAs/SM, 2 sweeps)
    k2_mma<<<dim3(4, 4, CDIM), 256, smem2>>>();

    // 3) folded-LN out projection + gating (2 CTAs/SM)
    k3_mma<<<NN / 64, 256, smem3>>>(b_out, out);
}